// round 2
// baseline (speedup 1.0000x reference)
#include <cuda_runtime.h>
#include <math.h>

namespace cfg {
constexpr int B = 4, N = 8192, M = 1024, NS = 16;
constexpr int C1IN = 67, C3 = 256;
constexpr int CATT = 272, CAIN = 259;   // 8 q + 8 k + 256 v
constexpr int CF = 256, CO = 512;
constexpr int SLAB = B * 16;
constexpr int O1 = 0, O2 = 64, O3 = 192, OP = 448, OO = 704, OTOT = 1216;
}
using namespace cfg;

__device__ float d_featin[(size_t)B * C1IN * N];
__device__ float d_z1[(size_t)B * 64 * N];
__device__ float d_z2[(size_t)B * 128 * N];
__device__ float d_z3[(size_t)B * 256 * N];
__device__ float d_nft[(size_t)B * N * C3];
__device__ int   d_idx1[B * M * NS];
__device__ int   d_idx2[B * M * NS];
__device__ float d_ipt[(size_t)SLAB * CAIN * M];
__device__ float d_wqkv[CATT * CAIN];
__device__ float d_qkvt[(size_t)SLAB * CATT * M];
__device__ float d_mx[SLAB * M];
__device__ float d_ri[SLAB * M];
__device__ float d_af[(size_t)SLAB * CF * M];
__device__ float d_zf[(size_t)SLAB * CF * M];
__device__ float d_pooled[(size_t)B * CF * M];
__device__ float d_zo[(size_t)B * CO * M];
__device__ float d_bnsc[OTOT];
__device__ float d_bnsh[OTOT];

__global__ void prep_featin_k(const float* __restrict__ xyz, const float* __restrict__ feat) {
    int i = blockIdx.x * 256 + threadIdx.x;
    if (i >= B * C1IN * N) return;
    int n = i % N, c = (i / N) % C1IN, b = i / (N * C1IN);
    d_featin[i] = (c < 3) ? xyz[((size_t)b * N + n) * 3 + c]
                          : feat[((size_t)b * 64 + (c - 3)) * N + n];
}

__global__ void wqkv_k(const float* __restrict__ Wq, const float* __restrict__ Wk,
                       const float* __restrict__ Wv) {
    int i = blockIdx.x * 256 + threadIdx.x;
    if (i >= CATT * CAIN) return;
    int r = i / CAIN, c = i % CAIN;
    float v;
    if (r < 8)       v = Wq[r * CAIN + c];
    else if (r < 16) v = Wk[(r - 8) * CAIN + c];
    else             v = Wv[(r - 16) * CAIN + c];
    d_wqkv[i] = v;
}

// deterministic per-channel mean/var over [nslab][Cc][S]; writes folded scale/shift
__global__ __launch_bounds__(256) void stats_k(const float* __restrict__ z,
                                               const float* __restrict__ g,
                                               const float* __restrict__ bb,
                                               int bnoff, int nslab, int Cc, int S) {
    int c = blockIdx.x, t = threadIdx.x;
    float s1 = 0.f, s2 = 0.f;
    for (int u = 0; u < nslab; u++) {
        const float* p = z + ((size_t)u * Cc + c) * S;
        for (int i = t; i < S; i += 256) { float x = p[i]; s1 += x; s2 += x * x; }
    }
    __shared__ float a1[256], a2[256];
    a1[t] = s1; a2[t] = s2; __syncthreads();
    for (int off = 128; off; off >>= 1) {
        if (t < off) { a1[t] += a1[t + off]; a2[t] += a2[t + off]; }
        __syncthreads();
    }
    if (t == 0) {
        float cnt = (float)nslab * (float)S;
        float mu = a1[0] / cnt;
        float var = a2[0] / cnt - mu * mu;
        float s = g[c] * rsqrtf(var + 1e-5f);
        d_bnsc[bnoff + c] = s;
        d_bnsh[bnoff + c] = bb[c] - mu * s;
    }
}

// Z[b][o][j] = sum_k W[o][k] * f(X[b][k][j])
// MODE 0: identity. MODE 1: relu(bn) of prev layer. MODE 2: X - X2.
template <int MODE>
__global__ __launch_bounds__(256) void gemm_k(const float* __restrict__ W,
                                              const float* __restrict__ X,
                                              const float* __restrict__ X2,
                                              float* __restrict__ Z,
                                              int Cout, int Cin, int S,
                                              size_t xbs, size_t x2bs, size_t zbs,
                                              int bnoff) {
    __shared__ float Wt[16][68];
    __shared__ float Xt[16][68];
    int b = blockIdx.z, j0 = blockIdx.x * 64, o0 = blockIdx.y * 64;
    const float* Xb = X + (size_t)b * xbs;
    const float* X2b = (MODE == 2) ? (X2 + (size_t)b * x2bs) : nullptr;
    int tid = threadIdx.x, tx = tid & 15, ty = tid >> 4;
    float acc[4][4] = {};
    int nkt = (Cin + 15) >> 4;
    for (int kt = 0; kt < nkt; kt++) {
        int k0 = kt * 16;
#pragma unroll
        for (int i = 0; i < 4; i++) {
            int e = tid + i * 256, kk = e & 15, oo = e >> 4;
            int o = o0 + oo, k = k0 + kk;
            Wt[kk][oo] = (o < Cout && k < Cin) ? W[(size_t)o * Cin + k] : 0.f;
        }
#pragma unroll
        for (int i = 0; i < 4; i++) {
            int e = tid + i * 256, jj = e & 63, kk = e >> 6;
            int k = k0 + kk;
            float v = 0.f;
            if (k < Cin) {
                v = Xb[(size_t)k * S + j0 + jj];
                if (MODE == 1) v = fmaxf(d_bnsc[bnoff + k] * v + d_bnsh[bnoff + k], 0.f);
                else if (MODE == 2) v = v - X2b[(size_t)k * S + j0 + jj];
            }
            Xt[kk][jj] = v;
        }
        __syncthreads();
#pragma unroll
        for (int kk = 0; kk < 16; kk++) {
            float4 a = *(const float4*)&Wt[kk][ty * 4];
            float4 x = *(const float4*)&Xt[kk][tx * 4];
            acc[0][0] += a.x * x.x; acc[0][1] += a.x * x.y; acc[0][2] += a.x * x.z; acc[0][3] += a.x * x.w;
            acc[1][0] += a.y * x.x; acc[1][1] += a.y * x.y; acc[1][2] += a.y * x.z; acc[1][3] += a.y * x.w;
            acc[2][0] += a.z * x.x; acc[2][1] += a.z * x.y; acc[2][2] += a.z * x.z; acc[2][3] += a.z * x.w;
            acc[3][0] += a.w * x.x; acc[3][1] += a.w * x.y; acc[3][2] += a.w * x.z; acc[3][3] += a.w * x.w;
        }
        __syncthreads();
    }
#pragma unroll
    for (int i = 0; i < 4; i++) {
        int o = o0 + ty * 4 + i;
        if (o < Cout) {
            float4 v = make_float4(acc[i][0], acc[i][1], acc[i][2], acc[i][3]);
            *(float4*)&Z[(size_t)b * zbs + (size_t)o * S + j0 + tx * 4] = v;
        }
    }
}

// z3 -> nft[b][n][c] transpose with bn+relu folded
__global__ void nft_k() {
    __shared__ float t[32][33];
    int b = blockIdx.z, c0 = blockIdx.y * 32, n0 = blockIdx.x * 32;
    int tx = threadIdx.x, ty = threadIdx.y;
#pragma unroll
    for (int r = 0; r < 4; r++) {
        int c = c0 + ty + r * 8;
        float v = d_z3[((size_t)b * C3 + c) * N + n0 + tx];
        t[ty + r * 8][tx] = fmaxf(d_bnsc[O3 + c] * v + d_bnsh[O3 + c], 0.f);
    }
    __syncthreads();
#pragma unroll
    for (int r = 0; r < 4; r++) {
        int n = n0 + ty + r * 8;
        d_nft[((size_t)b * N + n) * C3 + c0 + tx] = t[tx][ty + r * 8];
    }
}

// ball query: warp per center, ordered ballot-scan, early exit at 16 hits
__global__ __launch_bounds__(256) void ballq_k(const float* __restrict__ pts, int Ns,
                                               const float* __restrict__ ctr,
                                               int* __restrict__ idx) {
    int w = (blockIdx.x << 3) + (threadIdx.x >> 5);
    int lane = threadIdx.x & 31;
    int b = w >> 10, m = w & 1023;
    __shared__ int lst[8][16];
    int* mylst = lst[threadIdx.x >> 5];
    float cx = ctr[((size_t)b * M + m) * 3 + 0];
    float cy = ctr[((size_t)b * M + m) * 3 + 1];
    float cz = ctr[((size_t)b * M + m) * 3 + 2];
    int cnt = 0;
    for (int base = 0; base < Ns && cnt < 16; base += 32) {
        int n = base + lane;
        bool in = false;
        if (n < Ns) {
            float dx = __fsub_rn(cx, pts[((size_t)b * Ns + n) * 3 + 0]);
            float dy = __fsub_rn(cy, pts[((size_t)b * Ns + n) * 3 + 1]);
            float dz = __fsub_rn(cz, pts[((size_t)b * Ns + n) * 3 + 2]);
            float d2 = __fadd_rn(__fadd_rn(__fmul_rn(dx, dx), __fmul_rn(dy, dy)), __fmul_rn(dz, dz));
            in = d2 < 0.25f;
        }
        unsigned mask = __ballot_sync(0xffffffffu, in);
        if (in) {
            int r = cnt + __popc(mask & ((1u << lane) - 1u));
            if (r < 16) mylst[r] = n;
        }
        cnt += __popc(mask);
    }
    __syncwarp();
    if (lane < 16) {
        int c = cnt < 16 ? cnt : 16;
        int v = (cnt == 0) ? 0 : mylst[lane < c ? lane : 0];
        idx[((size_t)b * M + m) * NS + lane] = v;
    }
}

// build ip_t[slab][c][m]: rows 0..255 grouped feats, 256..258 rel
__global__ __launch_bounds__(256) void group_k(const float* __restrict__ xyz,
                                               const float* __restrict__ ctr) {
    __shared__ float tile[32][257];
    __shared__ int cols[32], cols2[32];
    int b = blockIdx.z, s = blockIdx.y, m0 = blockIdx.x * 32, tid = threadIdx.x;
    if (tid < 32) {
        cols[tid]  = d_idx1[((b * M) + m0 + tid) * NS + s];
        cols2[tid] = d_idx2[((b * M) + m0 + tid) * NS + s];
    }
    __syncthreads();
    for (int i = 0; i < 32; i++)
        tile[i][tid] = d_nft[((size_t)b * N + cols[i]) * C3 + tid];
    __syncthreads();
    size_t base = ((size_t)(b * 16 + s) * CAIN) * M + m0;
    for (int i = 0; i < 32; i++) {
        int e = i * 256 + tid, c = e >> 5, mm = e & 31;
        d_ipt[base + (size_t)c * M + mm] = tile[mm][c];
    }
    if (tid < 32) {
        int c1 = cols[tid], c2 = cols2[tid];
#pragma unroll
        for (int ax = 0; ax < 3; ax++)
            d_ipt[base + (size_t)(C3 + ax) * M + tid] =
                ctr[((size_t)b * M + c2) * 3 + ax] - xyz[((size_t)b * N + c1) * 3 + ax];
    }
}

// attention pass1: per-column max & 1/sumexp of S = K^T Q (rank-8)
__global__ __launch_bounds__(256) void pass1_k() {
    __shared__ float Kst[8 * 1024];   // [n][8]
    int slab = blockIdx.y, tid = threadIdx.x;
    const float* base = d_qkvt + (size_t)slab * CATT * M;
    const float* kt = base + 8 * M;
    for (int i = tid; i < 8 * M; i += 256) {
        int c = i >> 10, n = i & 1023;
        Kst[n * 8 + c] = kt[i];
    }
    __syncthreads();
    int j = blockIdx.x * 256 + tid;
    float q[8];
#pragma unroll
    for (int c = 0; c < 8; c++) q[c] = base[c * M + j];
    float mx = -1e30f;
    for (int n = 0; n < M; n++) {
        float4 k0 = *(const float4*)&Kst[n * 8];
        float4 k1 = *(const float4*)&Kst[n * 8 + 4];
        float s = k0.x * q[0] + k0.y * q[1] + k0.z * q[2] + k0.w * q[3]
                + k1.x * q[4] + k1.y * q[5] + k1.z * q[6] + k1.w * q[7];
        mx = fmaxf(mx, s);
    }
    float sum = 0.f;
    for (int n = 0; n < M; n++) {
        float4 k0 = *(const float4*)&Kst[n * 8];
        float4 k1 = *(const float4*)&Kst[n * 8 + 4];
        float s = k0.x * q[0] + k0.y * q[1] + k0.z * q[2] + k0.w * q[3]
                + k1.x * q[4] + k1.y * q[5] + k1.z * q[6] + k1.w * q[7];
        sum += __expf(s - mx);
    }
    d_mx[slab * M + j] = mx;
    d_ri[slab * M + j] = 1.f / sum;
}

// attention pass2: AF[64c x 64j] tile = V @ P with P recomputed on the fly
__global__ __launch_bounds__(256) void pass2_k() {
    __shared__ float Qs[8][64];
    __shared__ float Ksh[16][8];
    __shared__ float Ps[16][68];
    __shared__ float Vs[16][68];
    __shared__ float mxs[64], ris[64];
    int slab = blockIdx.z, c0 = blockIdx.y * 64, j0 = blockIdx.x * 64;
    int tid = threadIdx.x, tx = tid & 15, ty = tid >> 4;
    const float* base = d_qkvt + (size_t)slab * CATT * M;
    for (int i = tid; i < 512; i += 256) {
        int c = i >> 6, jj = i & 63;
        Qs[c][jj] = base[c * M + j0 + jj];
    }
    if (tid < 64) {
        mxs[tid] = d_mx[slab * M + j0 + tid];
        ris[tid] = d_ri[slab * M + j0 + tid];
    }
    __syncthreads();
    float acc[4][4] = {};
    for (int nt = 0; nt < M; nt += 16) {
        if (tid < 128) {
            int kk = tid >> 3, c = tid & 7;
            Ksh[kk][c] = base[(8 + c) * M + nt + kk];
        }
#pragma unroll
        for (int i = 0; i < 4; i++) {
            int e = tid + i * 256, cc = e >> 4, kk = e & 15;
            Vs[kk][cc] = base[(16 + c0 + cc) * M + nt + kk];
        }
        __syncthreads();
#pragma unroll
        for (int i = 0; i < 4; i++) {
            int e = tid + i * 256, kk = e >> 6, jj = e & 63;
            float s = 0.f;
#pragma unroll
            for (int c = 0; c < 8; c++) s += Ksh[kk][c] * Qs[c][jj];
            Ps[kk][jj] = __expf(s - mxs[jj]) * ris[jj];
        }
        __syncthreads();
#pragma unroll
        for (int kk = 0; kk < 16; kk++) {
            float4 a = *(const float4*)&Vs[kk][ty * 4];
            float4 x = *(const float4*)&Ps[kk][tx * 4];
            acc[0][0] += a.x * x.x; acc[0][1] += a.x * x.y; acc[0][2] += a.x * x.z; acc[0][3] += a.x * x.w;
            acc[1][0] += a.y * x.x; acc[1][1] += a.y * x.y; acc[1][2] += a.y * x.z; acc[1][3] += a.y * x.w;
            acc[2][0] += a.z * x.x; acc[2][1] += a.z * x.y; acc[2][2] += a.z * x.z; acc[2][3] += a.z * x.w;
            acc[3][0] += a.w * x.x; acc[3][1] += a.w * x.y; acc[3][2] += a.w * x.z; acc[3][3] += a.w * x.w;
        }
        __syncthreads();
    }
#pragma unroll
    for (int i = 0; i < 4; i++) {
        int c = c0 + ty * 4 + i;
        float4 v = make_float4(acc[i][0], acc[i][1], acc[i][2], acc[i][3]);
        *(float4*)&d_af[(size_t)slab * CF * M + (size_t)c * M + j0 + tx * 4] = v;
    }
}

// pooled[b][c][m] = max_s( relu(bn(zf)) + group_features )
__global__ void pool_k() {
    int i = blockIdx.x * 256 + threadIdx.x;
    if (i >= B * C3 * M) return;
    int m = i & 1023, c = (i >> 10) & 255, b = i >> 18;
    float sc = d_bnsc[OP + c], sh = d_bnsh[OP + c];
    float acc = -1e30f;
    for (int s = 0; s < 16; s++) {
        size_t slab = (size_t)(b * 16 + s);
        float z = d_zf[slab * CF * M + (size_t)c * M + m];
        float gf = d_ipt[slab * CAIN * M + (size_t)c * M + m];
        acc = fmaxf(acc, fmaxf(sc * z + sh, 0.f) + gf);
    }
    d_pooled[((size_t)b * C3 + c) * M + m] = acc;
}

__global__ void out_k(float* __restrict__ out) {
    int i = blockIdx.x * 256 + threadIdx.x;
    if (i >= B * CO * M) return;
    int c = (i >> 10) & 511;
    float z = d_zo[i];
    out[i] = fmaxf(d_bnsc[OO + c] * z + d_bnsh[OO + c], 0.f);
}

__global__ void ctr_k(const float* __restrict__ ctr, float* __restrict__ out, int n) {
    int i = blockIdx.x * 256 + threadIdx.x;
    if (i < n) out[i] = ctr[i];
}

extern "C" void kernel_launch(void* const* d_in, const int* in_sizes, int n_in,
                              void* d_out, int out_size) {
    (void)in_sizes; (void)n_in;
    const float* xyz = (const float*)d_in[0];
    const float* feat = (const float*)d_in[1];
    const float* ctr = (const float*)d_in[2];
    const float* W1 = (const float*)d_in[3];
    const float* g1 = (const float*)d_in[4];
    const float* b1 = (const float*)d_in[5];
    const float* W2 = (const float*)d_in[6];
    const float* g2 = (const float*)d_in[7];
    const float* b2 = (const float*)d_in[8];
    const float* W3 = (const float*)d_in[9];
    const float* g3 = (const float*)d_in[10];
    const float* b3 = (const float*)d_in[11];
    const float* Wq = (const float*)d_in[12];
    const float* Wk = (const float*)d_in[13];
    const float* Wv = (const float*)d_in[14];
    const float* Wf = (const float*)d_in[15];
    const float* gp = (const float*)d_in[16];
    const float* bp = (const float*)d_in[17];
    const float* Wo = (const float*)d_in[18];
    const float* go = (const float*)d_in[19];
    const float* bo = (const float*)d_in[20];
    float* outp = (float*)d_out;

    float *p_featin, *p_z1, *p_z2, *p_z3, *p_ipt, *p_wqkv, *p_qkvt, *p_af, *p_zf, *p_pooled, *p_zo;
    int *p_idx1, *p_idx2;
    cudaGetSymbolAddress((void**)&p_featin, d_featin);
    cudaGetSymbolAddress((void**)&p_z1, d_z1);
    cudaGetSymbolAddress((void**)&p_z2, d_z2);
    cudaGetSymbolAddress((void**)&p_z3, d_z3);
    cudaGetSymbolAddress((void**)&p_ipt, d_ipt);
    cudaGetSymbolAddress((void**)&p_wqkv, d_wqkv);
    cudaGetSymbolAddress((void**)&p_qkvt, d_qkvt);
    cudaGetSymbolAddress((void**)&p_af, d_af);
    cudaGetSymbolAddress((void**)&p_zf, d_zf);
    cudaGetSymbolAddress((void**)&p_pooled, d_pooled);
    cudaGetSymbolAddress((void**)&p_zo, d_zo);
    cudaGetSymbolAddress((void**)&p_idx1, d_idx1);
    cudaGetSymbolAddress((void**)&p_idx2, d_idx2);

    // MLP chain on all N points
    prep_featin_k<<<(B * C1IN * N + 255) / 256, 256>>>(xyz, feat);
    wqkv_k<<<(CATT * CAIN + 255) / 256, 256>>>(Wq, Wk, Wv);
    gemm_k<0><<<dim3(N / 64, 1, B), 256>>>(W1, p_featin, nullptr, p_z1, 64, C1IN, N,
                                           (size_t)C1IN * N, 0, (size_t)64 * N, 0);
    stats_k<<<64, 256>>>(p_z1, g1, b1, O1, B, 64, N);
    gemm_k<1><<<dim3(N / 64, 2, B), 256>>>(W2, p_z1, nullptr, p_z2, 128, 64, N,
                                           (size_t)64 * N, 0, (size_t)128 * N, O1);
    stats_k<<<128, 256>>>(p_z2, g2, b2, O2, B, 128, N);
    gemm_k<1><<<dim3(N / 64, 4, B), 256>>>(W3, p_z2, nullptr, p_z3, 256, 128, N,
                                           (size_t)128 * N, 0, (size_t)256 * N, O2);
    stats_k<<<256, 256>>>(p_z3, g3, b3, O3, B, 256, N);
    nft_k<<<dim3(N / 32, C3 / 32, B), dim3(32, 8)>>>();

    // ball query + grouping
    ballq_k<<<B * M / 8, 256>>>(xyz, N, ctr, p_idx1);
    ballq_k<<<B * M / 8, 256>>>(ctr, M, ctr, p_idx2);
    group_k<<<dim3(M / 32, 16, B), 256>>>(xyz, ctr);

    // qkv projection (slot-major)
    gemm_k<0><<<dim3(M / 64, 5, SLAB), 256>>>(p_wqkv, p_ipt, nullptr, p_qkvt, CATT, CAIN, M,
                                              (size_t)CAIN * M, 0, (size_t)CATT * M, 0);
    // attention
    pass1_k<<<dim3(M / 256, SLAB), 256>>>();
    pass2_k<<<dim3(M / 64, CF / 64, SLAB), 256>>>();

    // Wf on offset = af - group_features
    gemm_k<2><<<dim3(M / 64, 4, SLAB), 256>>>(Wf, p_af, p_ipt, p_zf, 256, 256, M,
                                              (size_t)CF * M, (size_t)CAIN * M, (size_t)CF * M, 0);
    stats_k<<<256, 256>>>(p_zf, gp, bp, OP, SLAB, 256, M);
    pool_k<<<(B * C3 * M + 255) / 256, 256>>>();

    // final cbr
    gemm_k<0><<<dim3(M / 64, 8, B), 256>>>(Wo, p_pooled, nullptr, p_zo, 512, 256, M,
                                           (size_t)CF * M, 0, (size_t)CO * M, 0);
    stats_k<<<512, 256>>>(p_zo, go, bo, OO, B, 512, M);

    int off = out_size - B * CO * M;
    if (off > 0) ctr_k<<<(off + 255) / 256, 256>>>(ctr, outp, off);
    out_k<<<(B * CO * M + 255) / 256, 256>>>(outp + (off > 0 ? off : 0));
}

// round 5
// speedup vs baseline: 1.4616x; 1.4616x over previous
#include <cuda_runtime.h>
#include <math.h>
#include <stdint.h>

namespace cfg {
constexpr int B = 4, N = 8192, M = 1024, NS = 16;
constexpr int C1IN = 67, C3 = 256;
constexpr int CATT = 272, CAIN = 259;   // 8 q + 8 k + 256 v
constexpr int CF = 256, CO = 512;
constexpr int SLAB = B * 16;
constexpr int O1 = 0, O2 = 64, O3 = 192, OP = 448, OO = 704, OTOT = 1216;
}
using namespace cfg;

__device__ float d_featin[(size_t)B * C1IN * N];
__device__ float d_z1[(size_t)B * 64 * N];
__device__ float d_z2[(size_t)B * 128 * N];
__device__ float d_z3[(size_t)B * 256 * N];
__device__ float d_nft[(size_t)B * N * C3];
__device__ int   d_idx1[B * M * NS];
__device__ int   d_idx2[B * M * NS];
__device__ float d_ipt[(size_t)SLAB * CAIN * M];
__device__ float d_wqkv[CATT * CAIN];
__device__ float d_qkvt[(size_t)SLAB * CATT * M];
__device__ float d_mx[SLAB * M];
__device__ float d_ri[SLAB * M];
__device__ float d_af[(size_t)SLAB * CF * M];
__device__ float d_zf[(size_t)SLAB * CF * M];
__device__ float d_pooled[(size_t)B * CF * M];
__device__ float d_zo[(size_t)B * CO * M];
__device__ float d_bnsc[OTOT];
__device__ float d_bnsh[OTOT];

// ---------------- tf32 mma.sync helpers ----------------
__device__ __forceinline__ uint32_t f2tf(float f) {
    uint32_t u;
    asm("cvt.rna.tf32.f32 %0, %1;" : "=r"(u) : "f"(f));
    return u;
}
__device__ __forceinline__ void mma8(float* c, uint32_t a0, uint32_t a1, uint32_t a2, uint32_t a3,
                                     uint32_t b0, uint32_t b1) {
    asm volatile(
        "mma.sync.aligned.m16n8k8.row.col.f32.tf32.tf32.f32 "
        "{%0,%1,%2,%3}, {%4,%5,%6,%7}, {%8,%9}, {%0,%1,%2,%3};"
        : "+f"(c[0]), "+f"(c[1]), "+f"(c[2]), "+f"(c[3])
        : "r"(a0), "r"(a1), "r"(a2), "r"(a3), "r"(b0), "r"(b1));
}

// ---------------- misc prep ----------------
__global__ void prep_featin_k(const float* __restrict__ xyz, const float* __restrict__ feat) {
    int i = blockIdx.x * 256 + threadIdx.x;
    if (i >= B * C1IN * N) return;
    int n = i % N, c = (i / N) % C1IN, b = i / (N * C1IN);
    d_featin[i] = (c < 3) ? xyz[((size_t)b * N + n) * 3 + c]
                          : feat[((size_t)b * 64 + (c - 3)) * N + n];
}

__global__ void wqkv_k(const float* __restrict__ Wq, const float* __restrict__ Wk,
                       const float* __restrict__ Wv) {
    int i = blockIdx.x * 256 + threadIdx.x;
    if (i >= CATT * CAIN) return;
    int r = i / CAIN, c = i % CAIN;
    float v;
    if (r < 8)       v = Wq[r * CAIN + c];
    else if (r < 16) v = Wk[(r - 8) * CAIN + c];
    else             v = Wv[(r - 16) * CAIN + c];
    d_wqkv[i] = v;
}

__global__ __launch_bounds__(256) void stats_k(const float* __restrict__ z,
                                               const float* __restrict__ g,
                                               const float* __restrict__ bb,
                                               int bnoff, int nslab, int Cc, int S) {
    int c = blockIdx.x, t = threadIdx.x;
    float s1 = 0.f, s2 = 0.f;
    for (int u = 0; u < nslab; u++) {
        const float* p = z + ((size_t)u * Cc + c) * S;
        for (int i = t; i < S; i += 256) { float x = p[i]; s1 += x; s2 += x * x; }
    }
    __shared__ float a1[256], a2[256];
    a1[t] = s1; a2[t] = s2; __syncthreads();
    for (int off = 128; off; off >>= 1) {
        if (t < off) { a1[t] += a1[t + off]; a2[t] += a2[t + off]; }
        __syncthreads();
    }
    if (t == 0) {
        float cnt = (float)nslab * (float)S;
        float mu = a1[0] / cnt;
        float var = a2[0] / cnt - mu * mu;
        float s = g[c] * rsqrtf(var + 1e-5f);
        d_bnsc[bnoff + c] = s;
        d_bnsh[bnoff + c] = bb[c] - mu * s;
    }
}

// scalar fp32 GEMM (kept for accuracy-critical layers)
template <int MODE>
__global__ __launch_bounds__(256) void gemm_k(const float* __restrict__ W,
                                              const float* __restrict__ X,
                                              const float* __restrict__ X2,
                                              float* __restrict__ Z,
                                              int Cout, int Cin, int S,
                                              size_t xbs, size_t x2bs, size_t zbs,
                                              int bnoff) {
    __shared__ float Wt[16][68];
    __shared__ float Xt[16][68];
    int b = blockIdx.z, j0 = blockIdx.x * 64, o0 = blockIdx.y * 64;
    const float* Xb = X + (size_t)b * xbs;
    const float* X2b = (MODE == 2) ? (X2 + (size_t)b * x2bs) : nullptr;
    int tid = threadIdx.x, tx = tid & 15, ty = tid >> 4;
    float acc[4][4] = {};
    int nkt = (Cin + 15) >> 4;
    for (int kt = 0; kt < nkt; kt++) {
        int k0 = kt * 16;
#pragma unroll
        for (int i = 0; i < 4; i++) {
            int e = tid + i * 256, kk = e & 15, oo = e >> 4;
            int o = o0 + oo, k = k0 + kk;
            Wt[kk][oo] = (o < Cout && k < Cin) ? W[(size_t)o * Cin + k] : 0.f;
        }
#pragma unroll
        for (int i = 0; i < 4; i++) {
            int e = tid + i * 256, jj = e & 63, kk = e >> 6;
            int k = k0 + kk;
            float v = 0.f;
            if (k < Cin) {
                v = Xb[(size_t)k * S + j0 + jj];
                if (MODE == 1) v = fmaxf(d_bnsc[bnoff + k] * v + d_bnsh[bnoff + k], 0.f);
                else if (MODE == 2) v = v - X2b[(size_t)k * S + j0 + jj];
            }
            Xt[kk][jj] = v;
        }
        __syncthreads();
#pragma unroll
        for (int kk = 0; kk < 16; kk++) {
            float4 a = *(const float4*)&Wt[kk][ty * 4];
            float4 x = *(const float4*)&Xt[kk][tx * 4];
            acc[0][0] += a.x * x.x; acc[0][1] += a.x * x.y; acc[0][2] += a.x * x.z; acc[0][3] += a.x * x.w;
            acc[1][0] += a.y * x.x; acc[1][1] += a.y * x.y; acc[1][2] += a.y * x.z; acc[1][3] += a.y * x.w;
            acc[2][0] += a.z * x.x; acc[2][1] += a.z * x.y; acc[2][2] += a.z * x.z; acc[2][3] += a.z * x.w;
            acc[3][0] += a.w * x.x; acc[3][1] += a.w * x.y; acc[3][2] += a.w * x.z; acc[3][3] += a.w * x.w;
        }
        __syncthreads();
    }
#pragma unroll
    for (int i = 0; i < 4; i++) {
        int o = o0 + ty * 4 + i;
        if (o < Cout) {
            float4 v = make_float4(acc[i][0], acc[i][1], acc[i][2], acc[i][3]);
            *(float4*)&Z[(size_t)b * zbs + (size_t)o * S + j0 + tx * 4] = v;
        }
    }
}

// tf32 mma GEMM: Z[b][o][j] = sum_k W[o][k] * f(X[b][k][j]); 64x64 CTA tile, 8 warps of 16x32
template <int MODE>
__global__ __launch_bounds__(256) void gemm_tc(const float* __restrict__ W,
                                               const float* __restrict__ X,
                                               const float* __restrict__ X2,
                                               float* __restrict__ Z,
                                               int Cout, int Cin, int S,
                                               size_t xbs, size_t x2bs, size_t zbs,
                                               int bnoff) {
    __shared__ uint32_t Ws[64][20];
    __shared__ uint32_t Bs[16][72];
    int b = blockIdx.z, j0 = blockIdx.x * 64, o0 = blockIdx.y * 64;
    const float* Xb = X + (size_t)b * xbs;
    const float* X2b = (MODE == 2) ? (X2 + (size_t)b * x2bs) : nullptr;
    int tid = threadIdx.x, wid = tid >> 5, lane = tid & 31, g = lane >> 2, t4 = lane & 3;
    int ow = (wid & 3) * 16, jw = (wid >> 2) * 32;
    float acc[4][4] = {};
    int nkt = (Cin + 15) >> 4;
    for (int kt = 0; kt < nkt; kt++) {
        int k0 = kt * 16;
        __syncthreads();
#pragma unroll
        for (int i = 0; i < 4; i++) {
            int e = tid + i * 256, o = e >> 4, k = e & 15;
            float v = (o0 + o < Cout && k0 + k < Cin) ? W[(size_t)(o0 + o) * Cin + k0 + k] : 0.f;
            Ws[o][k] = f2tf(v);
        }
#pragma unroll
        for (int i = 0; i < 4; i++) {
            int e = tid + i * 256, k = e >> 6, j = e & 63;
            float v = 0.f;
            if (k0 + k < Cin) {
                v = Xb[(size_t)(k0 + k) * S + j0 + j];
                if (MODE == 1) v = fmaxf(d_bnsc[bnoff + k0 + k] * v + d_bnsh[bnoff + k0 + k], 0.f);
                else if (MODE == 2) v = v - X2b[(size_t)(k0 + k) * S + j0 + j];
            }
            Bs[k][j] = f2tf(v);
        }
        __syncthreads();
#pragma unroll
        for (int kk = 0; kk < 16; kk += 8) {
            uint32_t a0 = Ws[ow + g][kk + t4],     a1 = Ws[ow + 8 + g][kk + t4];
            uint32_t a2 = Ws[ow + g][kk + t4 + 4], a3 = Ws[ow + 8 + g][kk + t4 + 4];
#pragma unroll
            for (int jt = 0; jt < 4; jt++) {
                uint32_t b0 = Bs[kk + t4][jw + jt * 8 + g];
                uint32_t b1 = Bs[kk + t4 + 4][jw + jt * 8 + g];
                mma8(acc[jt], a0, a1, a2, a3, b0, b1);
            }
        }
    }
#pragma unroll
    for (int jt = 0; jt < 4; jt++) {
        int o = o0 + ow + g, j = j0 + jw + jt * 8 + 2 * t4;
        if (o < Cout) {
            float2 v = make_float2(acc[jt][0], acc[jt][1]);
            *(float2*)&Z[(size_t)b * zbs + (size_t)o * S + j] = v;
        }
        if (o + 8 < Cout) {
            float2 v = make_float2(acc[jt][2], acc[jt][3]);
            *(float2*)&Z[(size_t)b * zbs + (size_t)(o + 8) * S + j] = v;
        }
    }
}

__global__ void nft_k() {
    __shared__ float t[32][33];
    int b = blockIdx.z, c0 = blockIdx.y * 32, n0 = blockIdx.x * 32;
    int tx = threadIdx.x, ty = threadIdx.y;
#pragma unroll
    for (int r = 0; r < 4; r++) {
        int c = c0 + ty + r * 8;
        float v = d_z3[((size_t)b * C3 + c) * N + n0 + tx];
        t[ty + r * 8][tx] = fmaxf(d_bnsc[O3 + c] * v + d_bnsh[O3 + c], 0.f);
    }
    __syncthreads();
#pragma unroll
    for (int r = 0; r < 4; r++) {
        int n = n0 + ty + r * 8;
        d_nft[((size_t)b * N + n) * C3 + c0 + tx] = t[tx][ty + r * 8];
    }
}

__global__ __launch_bounds__(256) void ballq_k(const float* __restrict__ pts, int Ns,
                                               const float* __restrict__ ctr,
                                               int* __restrict__ idx) {
    int w = (blockIdx.x << 3) + (threadIdx.x >> 5);
    int lane = threadIdx.x & 31;
    int b = w >> 10, m = w & 1023;
    __shared__ int lst[8][16];
    int* mylst = lst[threadIdx.x >> 5];
    float cx = ctr[((size_t)b * M + m) * 3 + 0];
    float cy = ctr[((size_t)b * M + m) * 3 + 1];
    float cz = ctr[((size_t)b * M + m) * 3 + 2];
    int cnt = 0;
    for (int base = 0; base < Ns && cnt < 16; base += 32) {
        int n = base + lane;
        bool in = false;
        if (n < Ns) {
            float dx = __fsub_rn(cx, pts[((size_t)b * Ns + n) * 3 + 0]);
            float dy = __fsub_rn(cy, pts[((size_t)b * Ns + n) * 3 + 1]);
            float dz = __fsub_rn(cz, pts[((size_t)b * Ns + n) * 3 + 2]);
            float d2 = __fadd_rn(__fadd_rn(__fmul_rn(dx, dx), __fmul_rn(dy, dy)), __fmul_rn(dz, dz));
            in = d2 < 0.25f;
        }
        unsigned mask = __ballot_sync(0xffffffffu, in);
        if (in) {
            int r = cnt + __popc(mask & ((1u << lane) - 1u));
            if (r < 16) mylst[r] = n;
        }
        cnt += __popc(mask);
    }
    __syncwarp();
    if (lane < 16) {
        int c = cnt < 16 ? cnt : 16;
        int v = (cnt == 0) ? 0 : mylst[lane < c ? lane : 0];
        idx[((size_t)b * M + m) * NS + lane] = v;
    }
}

__global__ __launch_bounds__(256) void group_k(const float* __restrict__ xyz,
                                               const float* __restrict__ ctr) {
    __shared__ float tile[32][257];
    __shared__ int cols[32], cols2[32];
    int b = blockIdx.z, s = blockIdx.y, m0 = blockIdx.x * 32, tid = threadIdx.x;
    if (tid < 32) {
        cols[tid]  = d_idx1[((b * M) + m0 + tid) * NS + s];
        cols2[tid] = d_idx2[((b * M) + m0 + tid) * NS + s];
    }
    __syncthreads();
    for (int i = 0; i < 32; i++)
        tile[i][tid] = d_nft[((size_t)b * N + cols[i]) * C3 + tid];
    __syncthreads();
    size_t base = ((size_t)(b * 16 + s) * CAIN) * M + m0;
    for (int i = 0; i < 32; i++) {
        int e = i * 256 + tid, c = e >> 5, mm = e & 31;
        d_ipt[base + (size_t)c * M + mm] = tile[mm][c];
    }
    if (tid < 32) {
        int c1 = cols[tid], c2 = cols2[tid];
#pragma unroll
        for (int ax = 0; ax < 3; ax++)
            d_ipt[base + (size_t)(C3 + ax) * M + tid] =
                ctr[((size_t)b * M + c2) * 3 + ax] - xyz[((size_t)b * N + c1) * 3 + ax];
    }
}

__global__ __launch_bounds__(256) void pass1_k() {
    __shared__ float Kst[8 * 1024];
    int slab = blockIdx.y, tid = threadIdx.x;
    const float* base = d_qkvt + (size_t)slab * CATT * M;
    const float* kt = base + 8 * M;
    for (int i = tid; i < 8 * M; i += 256) {
        int c = i >> 10, n = i & 1023;
        Kst[n * 8 + c] = kt[i];
    }
    __syncthreads();
    int j = blockIdx.x * 256 + tid;
    float q[8];
#pragma unroll
    for (int c = 0; c < 8; c++) q[c] = base[c * M + j];
    float mx = -1e30f;
    for (int n = 0; n < M; n++) {
        float4 k0 = *(const float4*)&Kst[n * 8];
        float4 k1 = *(const float4*)&Kst[n * 8 + 4];
        float s = k0.x * q[0] + k0.y * q[1] + k0.z * q[2] + k0.w * q[3]
                + k1.x * q[4] + k1.y * q[5] + k1.z * q[6] + k1.w * q[7];
        mx = fmaxf(mx, s);
    }
    float sum = 0.f;
    for (int n = 0; n < M; n++) {
        float4 k0 = *(const float4*)&Kst[n * 8];
        float4 k1 = *(const float4*)&Kst[n * 8 + 4];
        float s = k0.x * q[0] + k0.y * q[1] + k0.z * q[2] + k0.w * q[3]
                + k1.x * q[4] + k1.y * q[5] + k1.z * q[6] + k1.w * q[7];
        sum += __expf(s - mx);
    }
    d_mx[slab * M + j] = mx;
    d_ri[slab * M + j] = 1.f / sum;
}

// attention pass2 via tf32 mma.sync: D[128c x 64j] = V @ P, P recomputed on the fly (fp32 scores)
__global__ __launch_bounds__(256) void pass2_mma() {
    __shared__ uint32_t Vs[128][36];   // stride 36 -> conflict-free A frag lds
    __shared__ uint32_t Ps[32][72];    // stride 72 -> conflict-free B frag lds
    __shared__ float Ksh[32][8];
    __shared__ float Qs[8][64];
    __shared__ float mxs[64], ris[64];
    int tid = threadIdx.x;
    int slab = blockIdx.z, c0 = blockIdx.y * 128, j0 = blockIdx.x * 64;
    const float* base = d_qkvt + (size_t)slab * CATT * M;
    for (int i = tid; i < 512; i += 256) Qs[i >> 6][i & 63] = base[(i >> 6) * M + j0 + (i & 63)];
    if (tid < 64) {
        mxs[tid] = d_mx[slab * M + j0 + tid];
        ris[tid] = d_ri[slab * M + j0 + tid];
    }
    int wid = tid >> 5, lane = tid & 31, g = lane >> 2, t4 = lane & 3;
    int cw = (wid & 3) * 32, jw = (wid >> 2) * 32;
    float acc[2][4][4] = {};
    for (int t = 0; t < 32; t++) {
        int nt = t * 32;
        __syncthreads();
        { int c = tid & 7, n = tid >> 3; Ksh[n][c] = base[(8 + c) * M + nt + n]; }
#pragma unroll
        for (int i = 0; i < 4; i++) {
            int e = tid + i * 256, c = e >> 3, n4 = (e & 7) * 4;
            float4 v = *(const float4*)&base[(size_t)(16 + c0 + c) * M + nt + n4];
            uint4 u = make_uint4(f2tf(v.x), f2tf(v.y), f2tf(v.z), f2tf(v.w));
            *(uint4*)&Vs[c][n4] = u;
        }
        __syncthreads();
#pragma unroll
        for (int i = 0; i < 8; i++) {
            int e = tid + i * 256, n = e >> 6, j = e & 63;
            const float* kr = Ksh[n];
            float s = kr[0] * Qs[0][j] + kr[1] * Qs[1][j] + kr[2] * Qs[2][j] + kr[3] * Qs[3][j]
                    + kr[4] * Qs[4][j] + kr[5] * Qs[5][j] + kr[6] * Qs[6][j] + kr[7] * Qs[7][j];
            Ps[n][j] = f2tf(__expf(s - mxs[j]) * ris[j]);
        }
        __syncthreads();
#pragma unroll
        for (int kk = 0; kk < 32; kk += 8) {
            uint32_t a[2][4], bfr[4][2];
#pragma unroll
            for (int mt = 0; mt < 2; mt++) {
                int r0 = cw + mt * 16 + g;
                a[mt][0] = Vs[r0][kk + t4];     a[mt][1] = Vs[r0 + 8][kk + t4];
                a[mt][2] = Vs[r0][kk + t4 + 4]; a[mt][3] = Vs[r0 + 8][kk + t4 + 4];
            }
#pragma unroll
            for (int jt = 0; jt < 4; jt++) {
                bfr[jt][0] = Ps[kk + t4][jw + jt * 8 + g];
                bfr[jt][1] = Ps[kk + t4 + 4][jw + jt * 8 + g];
            }
#pragma unroll
            for (int mt = 0; mt < 2; mt++)
#pragma unroll
                for (int jt = 0; jt < 4; jt++)
                    mma8(acc[mt][jt], a[mt][0], a[mt][1], a[mt][2], a[mt][3], bfr[jt][0], bfr[jt][1]);
        }
    }
    float* afb = d_af + (size_t)slab * CF * M;
#pragma unroll
    for (int mt = 0; mt < 2; mt++)
#pragma unroll
        for (int jt = 0; jt < 4; jt++) {
            int c = c0 + cw + mt * 16 + g;
            int j = j0 + jw + jt * 8 + 2 * t4;
            *(float2*)&afb[(size_t)c * M + j]       = make_float2(acc[mt][jt][0], acc[mt][jt][1]);
            *(float2*)&afb[(size_t)(c + 8) * M + j] = make_float2(acc[mt][jt][2], acc[mt][jt][3]);
        }
}

__global__ void pool_k() {
    int i = blockIdx.x * 256 + threadIdx.x;
    if (i >= B * C3 * M) return;
    int m = i & 1023, c = (i >> 10) & 255, b = i >> 18;
    float sc = d_bnsc[OP + c], sh = d_bnsh[OP + c];
    float acc = -1e30f;
    for (int s = 0; s < 16; s++) {
        size_t slab = (size_t)(b * 16 + s);
        float z = d_zf[slab * CF * M + (size_t)c * M + m];
        float gf = d_ipt[slab * CAIN * M + (size_t)c * M + m];
        acc = fmaxf(acc, fmaxf(sc * z + sh, 0.f) + gf);
    }
    d_pooled[((size_t)b * C3 + c) * M + m] = acc;
}

__global__ void out_k(float* __restrict__ out) {
    int i = blockIdx.x * 256 + threadIdx.x;
    if (i >= B * CO * M) return;
    int c = (i >> 10) & 511;
    float z = d_zo[i];
    out[i] = fmaxf(d_bnsc[OO + c] * z + d_bnsh[OO + c], 0.f);
}

__global__ void ctr_k(const float* __restrict__ ctr, float* __restrict__ out, int n) {
    int i = blockIdx.x * 256 + threadIdx.x;
    if (i < n) out[i] = ctr[i];
}

extern "C" void kernel_launch(void* const* d_in, const int* in_sizes, int n_in,
                              void* d_out, int out_size) {
    (void)in_sizes; (void)n_in;
    const float* xyz = (const float*)d_in[0];
    const float* feat = (const float*)d_in[1];
    const float* ctr = (const float*)d_in[2];
    const float* W1 = (const float*)d_in[3];
    const float* g1 = (const float*)d_in[4];
    const float* b1 = (const float*)d_in[5];
    const float* W2 = (const float*)d_in[6];
    const float* g2 = (const float*)d_in[7];
    const float* b2 = (const float*)d_in[8];
    const float* W3 = (const float*)d_in[9];
    const float* g3 = (const float*)d_in[10];
    const float* b3 = (const float*)d_in[11];
    const float* Wq = (const float*)d_in[12];
    const float* Wk = (const float*)d_in[13];
    const float* Wv = (const float*)d_in[14];
    const float* Wf = (const float*)d_in[15];
    const float* gp = (const float*)d_in[16];
    const float* bp = (const float*)d_in[17];
    const float* Wo = (const float*)d_in[18];
    const float* go = (const float*)d_in[19];
    const float* bo = (const float*)d_in[20];
    float* outp = (float*)d_out;

    float *p_featin, *p_z1, *p_z2, *p_z3, *p_ipt, *p_wqkv, *p_qkvt, *p_af, *p_zf, *p_pooled, *p_zo;
    int *p_idx1, *p_idx2;
    cudaGetSymbolAddress((void**)&p_featin, d_featin);
    cudaGetSymbolAddress((void**)&p_z1, d_z1);
    cudaGetSymbolAddress((void**)&p_z2, d_z2);
    cudaGetSymbolAddress((void**)&p_z3, d_z3);
    cudaGetSymbolAddress((void**)&p_ipt, d_ipt);
    cudaGetSymbolAddress((void**)&p_wqkv, d_wqkv);
    cudaGetSymbolAddress((void**)&p_qkvt, d_qkvt);
    cudaGetSymbolAddress((void**)&p_af, d_af);
    cudaGetSymbolAddress((void**)&p_zf, d_zf);
    cudaGetSymbolAddress((void**)&p_pooled, d_pooled);
    cudaGetSymbolAddress((void**)&p_zo, d_zo);
    cudaGetSymbolAddress((void**)&p_idx1, d_idx1);
    cudaGetSymbolAddress((void**)&p_idx2, d_idx2);

    prep_featin_k<<<(B * C1IN * N + 255) / 256, 256>>>(xyz, feat);
    wqkv_k<<<(CATT * CAIN + 255) / 256, 256>>>(Wq, Wk, Wv);
    gemm_k<0><<<dim3(N / 64, 1, B), 256>>>(W1, p_featin, nullptr, p_z1, 64, C1IN, N,
                                           (size_t)C1IN * N, 0, (size_t)64 * N, 0);
    stats_k<<<64, 256>>>(p_z1, g1, b1, O1, B, 64, N);
    gemm_k<1><<<dim3(N / 64, 2, B), 256>>>(W2, p_z1, nullptr, p_z2, 128, 64, N,
                                           (size_t)64 * N, 0, (size_t)128 * N, O1);
    stats_k<<<128, 256>>>(p_z2, g2, b2, O2, B, 128, N);
    gemm_k<1><<<dim3(N / 64, 4, B), 256>>>(W3, p_z2, nullptr, p_z3, 256, 128, N,
                                           (size_t)128 * N, 0, (size_t)256 * N, O2);
    stats_k<<<256, 256>>>(p_z3, g3, b3, O3, B, 256, N);
    nft_k<<<dim3(N / 32, C3 / 32, B), dim3(32, 8)>>>();

    ballq_k<<<B * M / 8, 256>>>(xyz, N, ctr, p_idx1);
    ballq_k<<<B * M / 8, 256>>>(ctr, M, ctr, p_idx2);
    group_k<<<dim3(M / 32, 16, B), 256>>>(xyz, ctr);

    gemm_k<0><<<dim3(M / 64, 5, SLAB), 256>>>(p_wqkv, p_ipt, nullptr, p_qkvt, CATT, CAIN, M,
                                              (size_t)CAIN * M, 0, (size_t)CATT * M, 0);
    pass1_k<<<dim3(M / 256, SLAB), 256>>>();
    pass2_mma<<<dim3(M / 64, CF / 128, SLAB), 256>>>();

    gemm_tc<2><<<dim3(M / 64, 4, SLAB), 256>>>(Wf, p_af, p_ipt, p_zf, 256, 256, M,
                                               (size_t)CF * M, (size_t)CAIN * M, (size_t)CF * M, 0);
    stats_k<<<256, 256>>>(p_zf, gp, bp, OP, SLAB, 256, M);
    pool_k<<<(B * C3 * M + 255) / 256, 256>>>();

    gemm_k<0><<<dim3(M / 64, 8, B), 256>>>(Wo, p_pooled, nullptr, p_zo, 512, 256, M,
                                           (size_t)CF * M, 0, (size_t)CO * M, 0);
    stats_k<<<512, 256>>>(p_zo, go, bo, OO, B, 512, M);

    int off = out_size - B * CO * M;
    if (off > 0) ctr_k<<<(off + 255) / 256, 256>>>(ctr, outp, off);
    out_k<<<(B * CO * M + 255) / 256, 256>>>(outp + (off > 0 ? off : 0));
}

// round 7
// speedup vs baseline: 1.6270x; 1.1131x over previous
#include <cuda_runtime.h>
#include <math.h>
#include <stdint.h>

namespace cfg {
constexpr int B = 4, N = 8192, M = 1024, NS = 16;
constexpr int C1IN = 67, C3 = 256;
constexpr int CATT = 272, CAIN = 259;   // 8 q + 8 k + 256 v
constexpr int CF = 256, CO = 512;
constexpr int SLAB = B * 16;
constexpr int O1 = 0, O2 = 64, O3 = 192, OP = 448, OO = 704, OTOT = 1216;
}
using namespace cfg;

__device__ float d_featin[(size_t)B * C1IN * N];
__device__ float d_z1[(size_t)B * 64 * N];
__device__ float d_z2[(size_t)B * 128 * N];
__device__ float d_z3[(size_t)B * 256 * N];
__device__ float d_nft[(size_t)B * N * C3];
__device__ int   d_idx1[B * M * NS];
__device__ int   d_idx2[B * M * NS];
__device__ float d_ipt[(size_t)SLAB * CAIN * M];
__device__ float d_wqkv[CATT * CAIN];
__device__ float d_qkvt[(size_t)SLAB * CATT * M];
__device__ float d_mx[SLAB * M];
__device__ float d_ri[SLAB * M];
__device__ float d_af[(size_t)SLAB * CF * M];
__device__ float d_zf[(size_t)SLAB * CF * M];
__device__ float d_pooled[(size_t)B * CF * M];
__device__ float d_zo[(size_t)B * CO * M];
__device__ float d_bnsc[OTOT];
__device__ float d_bnsh[OTOT];

// ---------------- tf32 mma.sync helpers ----------------
__device__ __forceinline__ uint32_t f2tf(float f) {
    uint32_t u;
    asm("cvt.rna.tf32.f32 %0, %1;" : "=r"(u) : "f"(f));
    return u;
}
__device__ __forceinline__ void mma8(float* c, uint32_t a0, uint32_t a1, uint32_t a2, uint32_t a3,
                                     uint32_t b0, uint32_t b1) {
    asm volatile(
        "mma.sync.aligned.m16n8k8.row.col.f32.tf32.tf32.f32 "
        "{%0,%1,%2,%3}, {%4,%5,%6,%7}, {%8,%9}, {%0,%1,%2,%3};"
        : "+f"(c[0]), "+f"(c[1]), "+f"(c[2]), "+f"(c[3])
        : "r"(a0), "r"(a1), "r"(a2), "r"(a3), "r"(b0), "r"(b1));
}

// ---------------- misc prep ----------------
__global__ void prep_featin_k(const float* __restrict__ xyz, const float* __restrict__ feat) {
    int i = blockIdx.x * 256 + threadIdx.x;
    if (i >= B * C1IN * N) return;
    int n = i % N, c = (i / N) % C1IN, b = i / (N * C1IN);
    d_featin[i] = (c < 3) ? xyz[((size_t)b * N + n) * 3 + c]
                          : feat[((size_t)b * 64 + (c - 3)) * N + n];
}

__global__ void wqkv_k(const float* __restrict__ Wq, const float* __restrict__ Wk,
                       const float* __restrict__ Wv) {
    int i = blockIdx.x * 256 + threadIdx.x;
    if (i >= CATT * CAIN) return;
    int r = i / CAIN, c = i % CAIN;
    float v;
    if (r < 8)       v = Wq[r * CAIN + c];
    else if (r < 16) v = Wk[(r - 8) * CAIN + c];
    else             v = Wv[(r - 16) * CAIN + c];
    d_wqkv[i] = v;
}

__global__ __launch_bounds__(256) void stats_k(const float* __restrict__ z,
                                               const float* __restrict__ g,
                                               const float* __restrict__ bb,
                                               int bnoff, int nslab, int Cc, int S) {
    int c = blockIdx.x, t = threadIdx.x;
    float s1 = 0.f, s2 = 0.f;
    for (int u = 0; u < nslab; u++) {
        const float* p = z + ((size_t)u * Cc + c) * S;
        for (int i = t; i < S; i += 256) { float x = p[i]; s1 += x; s2 += x * x; }
    }
    __shared__ float a1[256], a2[256];
    a1[t] = s1; a2[t] = s2; __syncthreads();
    for (int off = 128; off; off >>= 1) {
        if (t < off) { a1[t] += a1[t + off]; a2[t] += a2[t + off]; }
        __syncthreads();
    }
    if (t == 0) {
        float cnt = (float)nslab * (float)S;
        float mu = a1[0] / cnt;
        float var = a2[0] / cnt - mu * mu;
        float s = g[c] * rsqrtf(var + 1e-5f);
        d_bnsc[bnoff + c] = s;
        d_bnsh[bnoff + c] = bb[c] - mu * s;
    }
}

// scalar fp32 GEMM (accuracy-critical layers)
template <int MODE>
__global__ __launch_bounds__(256) void gemm_k(const float* __restrict__ W,
                                              const float* __restrict__ X,
                                              const float* __restrict__ X2,
                                              float* __restrict__ Z,
                                              int Cout, int Cin, int S,
                                              size_t xbs, size_t x2bs, size_t zbs,
                                              int bnoff) {
    __shared__ float Wt[16][68];
    __shared__ float Xt[16][68];
    int b = blockIdx.z, j0 = blockIdx.x * 64, o0 = blockIdx.y * 64;
    const float* Xb = X + (size_t)b * xbs;
    const float* X2b = (MODE == 2) ? (X2 + (size_t)b * x2bs) : nullptr;
    int tid = threadIdx.x, tx = tid & 15, ty = tid >> 4;
    float acc[4][4] = {};
    int nkt = (Cin + 15) >> 4;
    for (int kt = 0; kt < nkt; kt++) {
        int k0 = kt * 16;
#pragma unroll
        for (int i = 0; i < 4; i++) {
            int e = tid + i * 256, kk = e & 15, oo = e >> 4;
            int o = o0 + oo, k = k0 + kk;
            Wt[kk][oo] = (o < Cout && k < Cin) ? W[(size_t)o * Cin + k] : 0.f;
        }
#pragma unroll
        for (int i = 0; i < 4; i++) {
            int e = tid + i * 256, jj = e & 63, kk = e >> 6;
            int k = k0 + kk;
            float v = 0.f;
            if (k < Cin) {
                v = Xb[(size_t)k * S + j0 + jj];
                if (MODE == 1) v = fmaxf(d_bnsc[bnoff + k] * v + d_bnsh[bnoff + k], 0.f);
                else if (MODE == 2) v = v - X2b[(size_t)k * S + j0 + jj];
            }
            Xt[kk][jj] = v;
        }
        __syncthreads();
#pragma unroll
        for (int kk = 0; kk < 16; kk++) {
            float4 a = *(const float4*)&Wt[kk][ty * 4];
            float4 x = *(const float4*)&Xt[kk][tx * 4];
            acc[0][0] += a.x * x.x; acc[0][1] += a.x * x.y; acc[0][2] += a.x * x.z; acc[0][3] += a.x * x.w;
            acc[1][0] += a.y * x.x; acc[1][1] += a.y * x.y; acc[1][2] += a.y * x.z; acc[1][3] += a.y * x.w;
            acc[2][0] += a.z * x.x; acc[2][1] += a.z * x.y; acc[2][2] += a.z * x.z; acc[2][3] += a.z * x.w;
            acc[3][0] += a.w * x.x; acc[3][1] += a.w * x.y; acc[3][2] += a.w * x.z; acc[3][3] += a.w * x.w;
        }
        __syncthreads();
    }
#pragma unroll
    for (int i = 0; i < 4; i++) {
        int o = o0 + ty * 4 + i;
        if (o < Cout) {
            float4 v = make_float4(acc[i][0], acc[i][1], acc[i][2], acc[i][3]);
            *(float4*)&Z[(size_t)b * zbs + (size_t)o * S + j0 + tx * 4] = v;
        }
    }
}

// tf32 mma GEMM: 64x64 CTA tile, 8 warps of 16x32
template <int MODE>
__global__ __launch_bounds__(256) void gemm_tc(const float* __restrict__ W,
                                               const float* __restrict__ X,
                                               const float* __restrict__ X2,
                                               float* __restrict__ Z,
                                               int Cout, int Cin, int S,
                                               size_t xbs, size_t x2bs, size_t zbs,
                                               int bnoff) {
    __shared__ uint32_t Ws[64][20];
    __shared__ uint32_t Bs[16][72];
    int b = blockIdx.z, j0 = blockIdx.x * 64, o0 = blockIdx.y * 64;
    const float* Xb = X + (size_t)b * xbs;
    const float* X2b = (MODE == 2) ? (X2 + (size_t)b * x2bs) : nullptr;
    int tid = threadIdx.x, wid = tid >> 5, lane = tid & 31, g = lane >> 2, t4 = lane & 3;
    int ow = (wid & 3) * 16, jw = (wid >> 2) * 32;
    float acc[4][4] = {};
    int nkt = (Cin + 15) >> 4;
    for (int kt = 0; kt < nkt; kt++) {
        int k0 = kt * 16;
        __syncthreads();
#pragma unroll
        for (int i = 0; i < 4; i++) {
            int e = tid + i * 256, o = e >> 4, k = e & 15;
            float v = (o0 + o < Cout && k0 + k < Cin) ? W[(size_t)(o0 + o) * Cin + k0 + k] : 0.f;
            Ws[o][k] = f2tf(v);
        }
#pragma unroll
        for (int i = 0; i < 4; i++) {
            int e = tid + i * 256, k = e >> 6, j = e & 63;
            float v = 0.f;
            if (k0 + k < Cin) {
                v = Xb[(size_t)(k0 + k) * S + j0 + j];
                if (MODE == 1) v = fmaxf(d_bnsc[bnoff + k0 + k] * v + d_bnsh[bnoff + k0 + k], 0.f);
                else if (MODE == 2) v = v - X2b[(size_t)(k0 + k) * S + j0 + j];
            }
            Bs[k][j] = f2tf(v);
        }
        __syncthreads();
#pragma unroll
        for (int kk = 0; kk < 16; kk += 8) {
            uint32_t a0 = Ws[ow + g][kk + t4],     a1 = Ws[ow + 8 + g][kk + t4];
            uint32_t a2 = Ws[ow + g][kk + t4 + 4], a3 = Ws[ow + 8 + g][kk + t4 + 4];
#pragma unroll
            for (int jt = 0; jt < 4; jt++) {
                uint32_t b0 = Bs[kk + t4][jw + jt * 8 + g];
                uint32_t b1 = Bs[kk + t4 + 4][jw + jt * 8 + g];
                mma8(acc[jt], a0, a1, a2, a3, b0, b1);
            }
        }
    }
#pragma unroll
    for (int jt = 0; jt < 4; jt++) {
        int o = o0 + ow + g, j = j0 + jw + jt * 8 + 2 * t4;
        if (o < Cout) {
            float2 v = make_float2(acc[jt][0], acc[jt][1]);
            *(float2*)&Z[(size_t)b * zbs + (size_t)o * S + j] = v;
        }
        if (o + 8 < Cout) {
            float2 v = make_float2(acc[jt][2], acc[jt][3]);
            *(float2*)&Z[(size_t)b * zbs + (size_t)(o + 8) * S + j] = v;
        }
    }
}

// q/k projection: 16 out-rows, fp32 exact; one thread per j column
__global__ __launch_bounds__(256) void qk_k() {
    __shared__ float Wsh[CAIN][16];
    int slab = blockIdx.y, j = blockIdx.x * 256 + threadIdx.x;
    for (int i = threadIdx.x; i < 16 * CAIN; i += 256) {
        int r = i / CAIN, k = i % CAIN;
        Wsh[k][r] = d_wqkv[i];
    }
    __syncthreads();
    const float* Xb = d_ipt + (size_t)slab * CAIN * M;
    float acc[16] = {};
    for (int k = 0; k < CAIN; k++) {
        float x = Xb[(size_t)k * M + j];
#pragma unroll
        for (int o = 0; o < 16; o++) acc[o] += Wsh[k][o] * x;
    }
    float* Zb = d_qkvt + (size_t)slab * CATT * M;
#pragma unroll
    for (int o = 0; o < 16; o++) Zb[(size_t)o * M + j] = acc[o];
}

__global__ void nft_k() {
    __shared__ float t[32][33];
    int b = blockIdx.z, c0 = blockIdx.y * 32, n0 = blockIdx.x * 32;
    int tx = threadIdx.x, ty = threadIdx.y;
#pragma unroll
    for (int r = 0; r < 4; r++) {
        int c = c0 + ty + r * 8;
        float v = d_z3[((size_t)b * C3 + c) * N + n0 + tx];
        t[ty + r * 8][tx] = fmaxf(d_bnsc[O3 + c] * v + d_bnsh[O3 + c], 0.f);
    }
    __syncthreads();
#pragma unroll
    for (int r = 0; r < 4; r++) {
        int n = n0 + ty + r * 8;
        d_nft[((size_t)b * N + n) * C3 + c0 + tx] = t[tx][ty + r * 8];
    }
}

__global__ __launch_bounds__(256) void ballq_k(const float* __restrict__ pts, int Ns,
                                               const float* __restrict__ ctr,
                                               int* __restrict__ idx) {
    int w = (blockIdx.x << 3) + (threadIdx.x >> 5);
    int lane = threadIdx.x & 31;
    int b = w >> 10, m = w & 1023;
    __shared__ int lst[8][16];
    int* mylst = lst[threadIdx.x >> 5];
    float cx = ctr[((size_t)b * M + m) * 3 + 0];
    float cy = ctr[((size_t)b * M + m) * 3 + 1];
    float cz = ctr[((size_t)b * M + m) * 3 + 2];
    int cnt = 0;
    for (int base = 0; base < Ns && cnt < 16; base += 32) {
        int n = base + lane;
        bool in = false;
        if (n < Ns) {
            float dx = __fsub_rn(cx, pts[((size_t)b * Ns + n) * 3 + 0]);
            float dy = __fsub_rn(cy, pts[((size_t)b * Ns + n) * 3 + 1]);
            float dz = __fsub_rn(cz, pts[((size_t)b * Ns + n) * 3 + 2]);
            float d2 = __fadd_rn(__fadd_rn(__fmul_rn(dx, dx), __fmul_rn(dy, dy)), __fmul_rn(dz, dz));
            in = d2 < 0.25f;
        }
        unsigned mask = __ballot_sync(0xffffffffu, in);
        if (in) {
            int r = cnt + __popc(mask & ((1u << lane) - 1u));
            if (r < 16) mylst[r] = n;
        }
        cnt += __popc(mask);
    }
    __syncwarp();
    if (lane < 16) {
        int c = cnt < 16 ? cnt : 16;
        int v = (cnt == 0) ? 0 : mylst[lane < c ? lane : 0];
        idx[((size_t)b * M + m) * NS + lane] = v;
    }
}

__global__ __launch_bounds__(256) void group_k(const float* __restrict__ xyz,
                                               const float* __restrict__ ctr) {
    __shared__ float tile[32][257];
    __shared__ int cols[32], cols2[32];
    int b = blockIdx.z, s = blockIdx.y, m0 = blockIdx.x * 32, tid = threadIdx.x;
    if (tid < 32) {
        cols[tid]  = d_idx1[((b * M) + m0 + tid) * NS + s];
        cols2[tid] = d_idx2[((b * M) + m0 + tid) * NS + s];
    }
    __syncthreads();
    for (int i = 0; i < 32; i++)
        tile[i][tid] = d_nft[((size_t)b * N + cols[i]) * C3 + tid];
    __syncthreads();
    size_t base = ((size_t)(b * 16 + s) * CAIN) * M + m0;
    for (int i = 0; i < 32; i++) {
        int e = i * 256 + tid, c = e >> 5, mm = e & 31;
        d_ipt[base + (size_t)c * M + mm] = tile[mm][c];
    }
    if (tid < 32) {
        int c1 = cols[tid], c2 = cols2[tid];
#pragma unroll
        for (int ax = 0; ax < 3; ax++)
            d_ipt[base + (size_t)(C3 + ax) * M + tid] =
                ctr[((size_t)b * M + c2) * 3 + ax] - xyz[((size_t)b * N + c1) * 3 + ax];
    }
}

// pass1: single-pass online softmax stats (chunked scores in registers)
__global__ __launch_bounds__(256) void pass1_k() {
    __shared__ float Kst[8 * 1024];
    int slab = blockIdx.y, tid = threadIdx.x;
    const float* base = d_qkvt + (size_t)slab * CATT * M;
    const float* kt = base + 8 * M;
    for (int i = tid; i < 8 * M; i += 256) {
        int c = i >> 10, n = i & 1023;
        Kst[n * 8 + c] = kt[i];
    }
    __syncthreads();
    int j = blockIdx.x * 256 + tid;
    float q[8];
#pragma unroll
    for (int c = 0; c < 8; c++) q[c] = base[c * M + j];
    float mx = -1e30f, sum = 0.f;
    for (int nt = 0; nt < M; nt += 16) {
        float sv[16];
        float cmx = -1e30f;
#pragma unroll
        for (int u = 0; u < 16; u++) {
            const float* kr = &Kst[(nt + u) * 8];
            float s = kr[0] * q[0] + kr[1] * q[1] + kr[2] * q[2] + kr[3] * q[3]
                    + kr[4] * q[4] + kr[5] * q[5] + kr[6] * q[6] + kr[7] * q[7];
            sv[u] = s;
            cmx = fmaxf(cmx, s);
        }
        if (cmx > mx) {
            sum *= __expf(mx - cmx);
            mx = cmx;
        }
#pragma unroll
        for (int u = 0; u < 16; u++) sum += __expf(sv[u] - mx);
    }
    d_mx[slab * M + j] = mx;
    d_ri[slab * M + j] = 1.f / sum;
}

// attention pass2 via tf32 mma.sync: D[128c x 64j] = V @ P, P recomputed on the fly (fp32 scores)
__global__ __launch_bounds__(256) void pass2_mma() {
    __shared__ uint32_t Vs[128][36];
    __shared__ uint32_t Ps[32][72];
    __shared__ float Ksh[32][8];
    __shared__ float Qs[8][64];
    __shared__ float mxs[64], ris[64];
    int tid = threadIdx.x;
    int slab = blockIdx.z, c0 = blockIdx.y * 128, j0 = blockIdx.x * 64;
    const float* base = d_qkvt + (size_t)slab * CATT * M;
    for (int i = tid; i < 512; i += 256) Qs[i >> 6][i & 63] = base[(i >> 6) * M + j0 + (i & 63)];
    if (tid < 64) {
        mxs[tid] = d_mx[slab * M + j0 + tid];
        ris[tid] = d_ri[slab * M + j0 + tid];
    }
    int wid = tid >> 5, lane = tid & 31, g = lane >> 2, t4 = lane & 3;
    int cw = (wid & 3) * 32, jw = (wid >> 2) * 32;
    float acc[2][4][4] = {};
    for (int t = 0; t < 32; t++) {
        int nt = t * 32;
        __syncthreads();
        { int c = tid & 7, n = tid >> 3; Ksh[n][c] = base[(8 + c) * M + nt + n]; }
#pragma unroll
        for (int i = 0; i < 4; i++) {
            int e = tid + i * 256, c = e >> 3, n4 = (e & 7) * 4;
            float4 v = *(const float4*)&base[(size_t)(16 + c0 + c) * M + nt + n4];
            uint4 u = make_uint4(f2tf(v.x), f2tf(v.y), f2tf(v.z), f2tf(v.w));
            *(uint4*)&Vs[c][n4] = u;
        }
        __syncthreads();
#pragma unroll
        for (int i = 0; i < 8; i++) {
            int e = tid + i * 256, n = e >> 6, j = e & 63;
            const float* kr = Ksh[n];
            float s = kr[0] * Qs[0][j] + kr[1] * Qs[1][j] + kr[2] * Qs[2][j] + kr[3] * Qs[3][j]
                    + kr[4] * Qs[4][j] + kr[5] * Qs[5][j] + kr[6] * Qs[6][j] + kr[7] * Qs[7][j];
            Ps[n][j] = f2tf(__expf(s - mxs[j]) * ris[j]);
        }
        __syncthreads();
#pragma unroll
        for (int kk = 0; kk < 32; kk += 8) {
            uint32_t a[2][4], bfr[4][2];
#pragma unroll
            for (int mt = 0; mt < 2; mt++) {
                int r0 = cw + mt * 16 + g;
                a[mt][0] = Vs[r0][kk + t4];     a[mt][1] = Vs[r0 + 8][kk + t4];
                a[mt][2] = Vs[r0][kk + t4 + 4]; a[mt][3] = Vs[r0 + 8][kk + t4 + 4];
            }
#pragma unroll
            for (int jt = 0; jt < 4; jt++) {
                bfr[jt][0] = Ps[kk + t4][jw + jt * 8 + g];
                bfr[jt][1] = Ps[kk + t4 + 4][jw + jt * 8 + g];
            }
#pragma unroll
            for (int mt = 0; mt < 2; mt++)
#pragma unroll
                for (int jt = 0; jt < 4; jt++)
                    mma8(acc[mt][jt], a[mt][0], a[mt][1], a[mt][2], a[mt][3], bfr[jt][0], bfr[jt][1]);
        }
    }
    float* afb = d_af + (size_t)slab * CF * M;
#pragma unroll
    for (int mt = 0; mt < 2; mt++)
#pragma unroll
        for (int jt = 0; jt < 4; jt++) {
            int c = c0 + cw + mt * 16 + g;
            int j = j0 + jw + jt * 8 + 2 * t4;
            *(float2*)&afb[(size_t)c * M + j]       = make_float2(acc[mt][jt][0], acc[mt][jt][1]);
            *(float2*)&afb[(size_t)(c + 8) * M + j] = make_float2(acc[mt][jt][2], acc[mt][jt][3]);
        }
}

__global__ void pool_k() {
    int i = blockIdx.x * 256 + threadIdx.x;
    if (i >= B * C3 * M) return;
    int m = i & 1023, c = (i >> 10) & 255, b = i >> 18;
    float sc = d_bnsc[OP + c], sh = d_bnsh[OP + c];
    float acc = -1e30f;
    for (int s = 0; s < 16; s++) {
        size_t slab = (size_t)(b * 16 + s);
        float z = d_zf[slab * CF * M + (size_t)c * M + m];
        float gf = d_ipt[slab * CAIN * M + (size_t)c * M + m];
        acc = fmaxf(acc, fmaxf(sc * z + sh, 0.f) + gf);
    }
    d_pooled[((size_t)b * C3 + c) * M + m] = acc;
}

__global__ void out_k(float* __restrict__ out) {
    int i = blockIdx.x * 256 + threadIdx.x;
    if (i >= B * CO * M) return;
    int c = (i >> 10) & 511;
    float z = d_zo[i];
    out[i] = fmaxf(d_bnsc[OO + c] * z + d_bnsh[OO + c], 0.f);
}

__global__ void ctr_k(const float* __restrict__ ctr, float* __restrict__ out, int n) {
    int i = blockIdx.x * 256 + threadIdx.x;
    if (i < n) out[i] = ctr[i];
}

extern "C" void kernel_launch(void* const* d_in, const int* in_sizes, int n_in,
                              void* d_out, int out_size) {
    (void)in_sizes; (void)n_in;
    const float* xyz = (const float*)d_in[0];
    const float* feat = (const float*)d_in[1];
    const float* ctr = (const float*)d_in[2];
    const float* W1 = (const float*)d_in[3];
    const float* g1 = (const float*)d_in[4];
    const float* b1 = (const float*)d_in[5];
    const float* W2 = (const float*)d_in[6];
    const float* g2 = (const float*)d_in[7];
    const float* b2 = (const float*)d_in[8];
    const float* W3 = (const float*)d_in[9];
    const float* g3 = (const float*)d_in[10];
    const float* b3 = (const float*)d_in[11];
    const float* Wq = (const float*)d_in[12];
    const float* Wk = (const float*)d_in[13];
    const float* Wv = (const float*)d_in[14];
    const float* Wf = (const float*)d_in[15];
    const float* gp = (const float*)d_in[16];
    const float* bp = (const float*)d_in[17];
    const float* Wo = (const float*)d_in[18];
    const float* go = (const float*)d_in[19];
    const float* bo = (const float*)d_in[20];
    float* outp = (float*)d_out;

    float *p_featin, *p_z1, *p_z2, *p_z3, *p_ipt, *p_wqkv, *p_qkvt, *p_af, *p_zf, *p_pooled, *p_zo;
    int *p_idx1, *p_idx2;
    cudaGetSymbolAddress((void**)&p_featin, d_featin);
    cudaGetSymbolAddress((void**)&p_z1, d_z1);
    cudaGetSymbolAddress((void**)&p_z2, d_z2);
    cudaGetSymbolAddress((void**)&p_z3, d_z3);
    cudaGetSymbolAddress((void**)&p_ipt, d_ipt);
    cudaGetSymbolAddress((void**)&p_wqkv, d_wqkv);
    cudaGetSymbolAddress((void**)&p_qkvt, d_qkvt);
    cudaGetSymbolAddress((void**)&p_af, d_af);
    cudaGetSymbolAddress((void**)&p_zf, d_zf);
    cudaGetSymbolAddress((void**)&p_pooled, d_pooled);
    cudaGetSymbolAddress((void**)&p_zo, d_zo);
    cudaGetSymbolAddress((void**)&p_idx1, d_idx1);
    cudaGetSymbolAddress((void**)&p_idx2, d_idx2);

    prep_featin_k<<<(B * C1IN * N + 255) / 256, 256>>>(xyz, feat);
    wqkv_k<<<(CATT * CAIN + 255) / 256, 256>>>(Wq, Wk, Wv);
    gemm_k<0><<<dim3(N / 64, 1, B), 256>>>(W1, p_featin, nullptr, p_z1, 64, C1IN, N,
                                           (size_t)C1IN * N, 0, (size_t)64 * N, 0);
    stats_k<<<64, 256>>>(p_z1, g1, b1, O1, B, 64, N);
    gemm_k<1><<<dim3(N / 64, 2, B), 256>>>(W2, p_z1, nullptr, p_z2, 128, 64, N,
                                           (size_t)64 * N, 0, (size_t)128 * N, O1);
    stats_k<<<128, 256>>>(p_z2, g2, b2, O2, B, 128, N);
    gemm_k<1><<<dim3(N / 64, 4, B), 256>>>(W3, p_z2, nullptr, p_z3, 256, 128, N,
                                           (size_t)128 * N, 0, (size_t)256 * N, O2);
    stats_k<<<256, 256>>>(p_z3, g3, b3, O3, B, 256, N);
    nft_k<<<dim3(N / 32, C3 / 32, B), dim3(32, 8)>>>();

    ballq_k<<<B * M / 8, 256>>>(xyz, N, ctr, p_idx1);
    ballq_k<<<B * M / 8, 256>>>(ctr, M, ctr, p_idx2);
    group_k<<<dim3(M / 32, 16, B), 256>>>(xyz, ctr);

    // q/k projection exact fp32; V projection tf32 tensor path
    qk_k<<<dim3(M / 256, SLAB), 256>>>();
    gemm_tc<0><<<dim3(M / 64, 4, SLAB), 256>>>(p_wqkv + 16 * CAIN, p_ipt, nullptr, p_qkvt + 16 * M,
                                               256, CAIN, M,
                                               (size_t)CAIN * M, 0, (size_t)CATT * M, 0);
    pass1_k<<<dim3(M / 256, SLAB), 256>>>();
    pass2_mma<<<dim3(M / 64, CF / 128, SLAB), 256>>>();

    gemm_tc<2><<<dim3(M / 64, 4, SLAB), 256>>>(Wf, p_af, p_ipt, p_zf, 256, 256, M,
                                               (size_t)CF * M, (size_t)CAIN * M, (size_t)CF * M, 0);
    stats_k<<<256, 256>>>(p_zf, gp, bp, OP, SLAB, 256, M);
    pool_k<<<(B * C3 * M + 255) / 256, 256>>>();

    gemm_k<0><<<dim3(M / 64, 8, B), 256>>>(Wo, p_pooled, nullptr, p_zo, 512, 256, M,
                                           (size_t)CF * M, 0, (size_t)CO * M, 0);
    stats_k<<<512, 256>>>(p_zo, go, bo, OO, B, 512, M);

    int off = out_size - B * CO * M;
    if (off > 0) ctr_k<<<(off + 255) / 256, 256>>>(ctr, outp, off);
    out_k<<<(B * CO * M + 255) / 256, 256>>>(outp + (off > 0 ? off : 0));
}

// round 11
// speedup vs baseline: 1.6460x; 1.0117x over previous
#include <cuda_runtime.h>
#include <math.h>
#include <stdint.h>

namespace cfg {
constexpr int B = 4, N = 8192, M = 1024, NS = 16;
constexpr int C1IN = 67, C3 = 256;
constexpr int CATT = 272, CAIN = 259;   // 8 q + 8 k + 256 v
constexpr int CF = 256, CO = 512;
constexpr int SLAB = B * 16;
constexpr int O1 = 0, O2 = 64, O3 = 192, OP = 448, OO = 704, OTOT = 1216;
}
using namespace cfg;

__device__ float d_featin[(size_t)B * C1IN * N];
__device__ float d_z1[(size_t)B * 64 * N];
__device__ float d_z2[(size_t)B * 128 * N];
__device__ float d_z3[(size_t)B * 256 * N];
__device__ float d_nft[(size_t)B * N * C3];
__device__ int   d_idx1[B * M * NS];
__device__ int   d_idx2[B * M * NS];
__device__ float d_ipt[(size_t)SLAB * CAIN * M];
__device__ float d_wqkv[CATT * CAIN];
__device__ float d_qkvt[(size_t)SLAB * CATT * M];
__device__ float d_mx[SLAB * M];
__device__ float d_ri[SLAB * M];
__device__ float d_af[(size_t)SLAB * CF * M];
__device__ float d_zf[(size_t)SLAB * CF * M];
__device__ float d_pooled[(size_t)B * CF * M];
__device__ float d_zo[(size_t)B * CO * M];
__device__ float d_bnsc[OTOT];
__device__ float d_bnsh[OTOT];

// ---------------- tf32 mma.sync helpers ----------------
__device__ __forceinline__ uint32_t f2tf(float f) {
    uint32_t u;
    asm("cvt.rna.tf32.f32 %0, %1;" : "=r"(u) : "f"(f));
    return u;
}
__device__ __forceinline__ void mma8(float* c, uint32_t a0, uint32_t a1, uint32_t a2, uint32_t a3,
                                     uint32_t b0, uint32_t b1) {
    asm volatile(
        "mma.sync.aligned.m16n8k8.row.col.f32.tf32.tf32.f32 "
        "{%0,%1,%2,%3}, {%4,%5,%6,%7}, {%8,%9}, {%0,%1,%2,%3};"
        : "+f"(c[0]), "+f"(c[1]), "+f"(c[2]), "+f"(c[3])
        : "r"(a0), "r"(a1), "r"(a2), "r"(a3), "r"(b0), "r"(b1));
}

// ---------------- misc prep ----------------
__global__ void prep_featin_k(const float* __restrict__ xyz, const float* __restrict__ feat) {
    int i = blockIdx.x * 256 + threadIdx.x;
    if (i >= B * C1IN * N) return;
    int n = i % N, c = (i / N) % C1IN, b = i / (N * C1IN);
    d_featin[i] = (c < 3) ? xyz[((size_t)b * N + n) * 3 + c]
                          : feat[((size_t)b * 64 + (c - 3)) * N + n];
}

__global__ void wqkv_k(const float* __restrict__ Wq, const float* __restrict__ Wk,
                       const float* __restrict__ Wv) {
    int i = blockIdx.x * 256 + threadIdx.x;
    if (i >= CATT * CAIN) return;
    int r = i / CAIN, c = i % CAIN;
    float v;
    if (r < 8)       v = Wq[r * CAIN + c];
    else if (r < 16) v = Wk[(r - 8) * CAIN + c];
    else             v = Wv[(r - 16) * CAIN + c];
    d_wqkv[i] = v;
}

__global__ __launch_bounds__(256) void stats_k(const float* __restrict__ z,
                                               const float* __restrict__ g,
                                               const float* __restrict__ bb,
                                               int bnoff, int nslab, int Cc, int S) {
    int c = blockIdx.x, t = threadIdx.x;
    float s1 = 0.f, s2 = 0.f;
    for (int u = 0; u < nslab; u++) {
        const float* p = z + ((size_t)u * Cc + c) * S;
        for (int i = t; i < S; i += 256) { float x = p[i]; s1 += x; s2 += x * x; }
    }
    __shared__ float a1[256], a2[256];
    a1[t] = s1; a2[t] = s2; __syncthreads();
    for (int off = 128; off; off >>= 1) {
        if (t < off) { a1[t] += a1[t + off]; a2[t] += a2[t + off]; }
        __syncthreads();
    }
    if (t == 0) {
        float cnt = (float)nslab * (float)S;
        float mu = a1[0] / cnt;
        float var = a2[0] / cnt - mu * mu;
        float s = g[c] * rsqrtf(var + 1e-5f);
        d_bnsc[bnoff + c] = s;
        d_bnsh[bnoff + c] = bb[c] - mu * s;
    }
}

// scalar fp32 GEMM (accuracy-critical layers)
template <int MODE>
__global__ __launch_bounds__(256) void gemm_k(const float* __restrict__ W,
                                              const float* __restrict__ X,
                                              const float* __restrict__ X2,
                                              float* __restrict__ Z,
                                              int Cout, int Cin, int S,
                                              size_t xbs, size_t x2bs, size_t zbs,
                                              int bnoff) {
    __shared__ float Wt[16][68];
    __shared__ float Xt[16][68];
    int b = blockIdx.z, j0 = blockIdx.x * 64, o0 = blockIdx.y * 64;
    const float* Xb = X + (size_t)b * xbs;
    const float* X2b = (MODE == 2) ? (X2 + (size_t)b * x2bs) : nullptr;
    int tid = threadIdx.x, tx = tid & 15, ty = tid >> 4;
    float acc[4][4] = {};
    int nkt = (Cin + 15) >> 4;
    for (int kt = 0; kt < nkt; kt++) {
        int k0 = kt * 16;
#pragma unroll
        for (int i = 0; i < 4; i++) {
            int e = tid + i * 256, kk = e & 15, oo = e >> 4;
            int o = o0 + oo, k = k0 + kk;
            Wt[kk][oo] = (o < Cout && k < Cin) ? W[(size_t)o * Cin + k] : 0.f;
        }
#pragma unroll
        for (int i = 0; i < 4; i++) {
            int e = tid + i * 256, jj = e & 63, kk = e >> 6;
            int k = k0 + kk;
            float v = 0.f;
            if (k < Cin) {
                v = Xb[(size_t)k * S + j0 + jj];
                if (MODE == 1) v = fmaxf(d_bnsc[bnoff + k] * v + d_bnsh[bnoff + k], 0.f);
                else if (MODE == 2) v = v - X2b[(size_t)k * S + j0 + jj];
            }
            Xt[kk][jj] = v;
        }
        __syncthreads();
#pragma unroll
        for (int kk = 0; kk < 16; kk++) {
            float4 a = *(const float4*)&Wt[kk][ty * 4];
            float4 x = *(const float4*)&Xt[kk][tx * 4];
            acc[0][0] += a.x * x.x; acc[0][1] += a.x * x.y; acc[0][2] += a.x * x.z; acc[0][3] += a.x * x.w;
            acc[1][0] += a.y * x.x; acc[1][1] += a.y * x.y; acc[1][2] += a.y * x.z; acc[1][3] += a.y * x.w;
            acc[2][0] += a.z * x.x; acc[2][1] += a.z * x.y; acc[2][2] += a.z * x.z; acc[2][3] += a.z * x.w;
            acc[3][0] += a.w * x.x; acc[3][1] += a.w * x.y; acc[3][2] += a.w * x.z; acc[3][3] += a.w * x.w;
        }
        __syncthreads();
    }
#pragma unroll
    for (int i = 0; i < 4; i++) {
        int o = o0 + ty * 4 + i;
        if (o < Cout) {
            float4 v = make_float4(acc[i][0], acc[i][1], acc[i][2], acc[i][3]);
            *(float4*)&Z[(size_t)b * zbs + (size_t)o * S + j0 + tx * 4] = v;
        }
    }
}

// tf32 mma GEMM: 64x64 CTA tile, 8 warps of 16x32
template <int MODE>
__global__ __launch_bounds__(256) void gemm_tc(const float* __restrict__ W,
                                               const float* __restrict__ X,
                                               const float* __restrict__ X2,
                                               float* __restrict__ Z,
                                               int Cout, int Cin, int S,
                                               size_t xbs, size_t x2bs, size_t zbs,
                                               int bnoff) {
    __shared__ uint32_t Ws[64][20];
    __shared__ uint32_t Bs[16][72];
    int b = blockIdx.z, j0 = blockIdx.x * 64, o0 = blockIdx.y * 64;
    const float* Xb = X + (size_t)b * xbs;
    const float* X2b = (MODE == 2) ? (X2 + (size_t)b * x2bs) : nullptr;
    int tid = threadIdx.x, wid = tid >> 5, lane = tid & 31, g = lane >> 2, t4 = lane & 3;
    int ow = (wid & 3) * 16, jw = (wid >> 2) * 32;
    float acc[4][4] = {};
    int nkt = (Cin + 15) >> 4;
    for (int kt = 0; kt < nkt; kt++) {
        int k0 = kt * 16;
        __syncthreads();
#pragma unroll
        for (int i = 0; i < 4; i++) {
            int e = tid + i * 256, o = e >> 4, k = e & 15;
            float v = (o0 + o < Cout && k0 + k < Cin) ? W[(size_t)(o0 + o) * Cin + k0 + k] : 0.f;
            Ws[o][k] = f2tf(v);
        }
#pragma unroll
        for (int i = 0; i < 4; i++) {
            int e = tid + i * 256, k = e >> 6, j = e & 63;
            float v = 0.f;
            if (k0 + k < Cin) {
                v = Xb[(size_t)(k0 + k) * S + j0 + j];
                if (MODE == 1) v = fmaxf(d_bnsc[bnoff + k0 + k] * v + d_bnsh[bnoff + k0 + k], 0.f);
                else if (MODE == 2) v = v - X2b[(size_t)(k0 + k) * S + j0 + j];
            }
            Bs[k][j] = f2tf(v);
        }
        __syncthreads();
#pragma unroll
        for (int kk = 0; kk < 16; kk += 8) {
            uint32_t a0 = Ws[ow + g][kk + t4],     a1 = Ws[ow + 8 + g][kk + t4];
            uint32_t a2 = Ws[ow + g][kk + t4 + 4], a3 = Ws[ow + 8 + g][kk + t4 + 4];
#pragma unroll
            for (int jt = 0; jt < 4; jt++) {
                uint32_t b0 = Bs[kk + t4][jw + jt * 8 + g];
                uint32_t b1 = Bs[kk + t4 + 4][jw + jt * 8 + g];
                mma8(acc[jt], a0, a1, a2, a3, b0, b1);
            }
        }
    }
#pragma unroll
    for (int jt = 0; jt < 4; jt++) {
        int o = o0 + ow + g, j = j0 + jw + jt * 8 + 2 * t4;
        if (o < Cout) {
            float2 v = make_float2(acc[jt][0], acc[jt][1]);
            *(float2*)&Z[(size_t)b * zbs + (size_t)o * S + j] = v;
        }
        if (o + 8 < Cout) {
            float2 v = make_float2(acc[jt][2], acc[jt][3]);
            *(float2*)&Z[(size_t)b * zbs + (size_t)(o + 8) * S + j] = v;
        }
    }
}

// q/k projection: 16 out-rows, fp32 exact; one thread per j column
__global__ __launch_bounds__(256) void qk_k() {
    __shared__ float Wsh[CAIN][16];
    int slab = blockIdx.y, j = blockIdx.x * 256 + threadIdx.x;
    for (int i = threadIdx.x; i < 16 * CAIN; i += 256) {
        int r = i / CAIN, k = i % CAIN;
        Wsh[k][r] = d_wqkv[i];
    }
    __syncthreads();
    const float* Xb = d_ipt + (size_t)slab * CAIN * M;
    float acc[16] = {};
    for (int k = 0; k < CAIN; k++) {
        float x = Xb[(size_t)k * M + j];
#pragma unroll
        for (int o = 0; o < 16; o++) acc[o] += Wsh[k][o] * x;
    }
    float* Zb = d_qkvt + (size_t)slab * CATT * M;
#pragma unroll
    for (int o = 0; o < 16; o++) Zb[(size_t)o * M + j] = acc[o];
}

__global__ void nft_k() {
    __shared__ float t[32][33];
    int b = blockIdx.z, c0 = blockIdx.y * 32, n0 = blockIdx.x * 32;
    int tx = threadIdx.x, ty = threadIdx.y;
#pragma unroll
    for (int r = 0; r < 4; r++) {
        int c = c0 + ty + r * 8;
        float v = d_z3[((size_t)b * C3 + c) * N + n0 + tx];
        t[ty + r * 8][tx] = fmaxf(d_bnsc[O3 + c] * v + d_bnsh[O3 + c], 0.f);
    }
    __syncthreads();
#pragma unroll
    for (int r = 0; r < 4; r++) {
        int n = n0 + ty + r * 8;
        d_nft[((size_t)b * N + n) * C3 + c0 + tx] = t[tx][ty + r * 8];
    }
}

__global__ __launch_bounds__(256) void ballq_k(const float* __restrict__ pts, int Ns,
                                               const float* __restrict__ ctr,
                                               int* __restrict__ idx) {
    int w = (blockIdx.x << 3) + (threadIdx.x >> 5);
    int lane = threadIdx.x & 31;
    int b = w >> 10, m = w & 1023;
    __shared__ int lst[8][16];
    int* mylst = lst[threadIdx.x >> 5];
    float cx = ctr[((size_t)b * M + m) * 3 + 0];
    float cy = ctr[((size_t)b * M + m) * 3 + 1];
    float cz = ctr[((size_t)b * M + m) * 3 + 2];
    int cnt = 0;
    for (int base = 0; base < Ns && cnt < 16; base += 32) {
        int n = base + lane;
        bool in = false;
        if (n < Ns) {
            float dx = __fsub_rn(cx, pts[((size_t)b * Ns + n) * 3 + 0]);
            float dy = __fsub_rn(cy, pts[((size_t)b * Ns + n) * 3 + 1]);
            float dz = __fsub_rn(cz, pts[((size_t)b * Ns + n) * 3 + 2]);
            float d2 = __fadd_rn(__fadd_rn(__fmul_rn(dx, dx), __fmul_rn(dy, dy)), __fmul_rn(dz, dz));
            in = d2 < 0.25f;
        }
        unsigned mask = __ballot_sync(0xffffffffu, in);
        if (in) {
            int r = cnt + __popc(mask & ((1u << lane) - 1u));
            if (r < 16) mylst[r] = n;
        }
        cnt += __popc(mask);
    }
    __syncwarp();
    if (lane < 16) {
        int c = cnt < 16 ? cnt : 16;
        int v = (cnt == 0) ? 0 : mylst[lane < c ? lane : 0];
        idx[((size_t)b * M + m) * NS + lane] = v;
    }
}

__global__ __launch_bounds__(256) void group_k(const float* __restrict__ xyz,
                                               const float* __restrict__ ctr) {
    __shared__ float tile[32][257];
    __shared__ int cols[32], cols2[32];
    int b = blockIdx.z, s = blockIdx.y, m0 = blockIdx.x * 32, tid = threadIdx.x;
    if (tid < 32) {
        cols[tid]  = d_idx1[((b * M) + m0 + tid) * NS + s];
        cols2[tid] = d_idx2[((b * M) + m0 + tid) * NS + s];
    }
    __syncthreads();
    for (int i = 0; i < 32; i++)
        tile[i][tid] = d_nft[((size_t)b * N + cols[i]) * C3 + tid];
    __syncthreads();
    size_t base = ((size_t)(b * 16 + s) * CAIN) * M + m0;
    for (int i = 0; i < 32; i++) {
        int e = i * 256 + tid, c = e >> 5, mm = e & 31;
        d_ipt[base + (size_t)c * M + mm] = tile[mm][c];
    }
    if (tid < 32) {
        int c1 = cols[tid], c2 = cols2[tid];
#pragma unroll
        for (int ax = 0; ax < 3; ax++)
            d_ipt[base + (size_t)(C3 + ax) * M + tid] =
                ctr[((size_t)b * M + c2) * 3 + ax] - xyz[((size_t)b * N + c1) * 3 + ax];
    }
}

// pass1: single-pass online softmax stats (chunked scores in registers)
__global__ __launch_bounds__(256) void pass1_k() {
    __shared__ float Kst[8 * 1024];
    int slab = blockIdx.y, tid = threadIdx.x;
    const float* base = d_qkvt + (size_t)slab * CATT * M;
    const float* kt = base + 8 * M;
    for (int i = tid; i < 8 * M; i += 256) {
        int c = i >> 10, n = i & 1023;
        Kst[n * 8 + c] = kt[i];
    }
    __syncthreads();
    int j = blockIdx.x * 256 + tid;
    float q[8];
#pragma unroll
    for (int c = 0; c < 8; c++) q[c] = base[c * M + j];
    float mx = -1e30f, sum = 0.f;
    for (int nt = 0; nt < M; nt += 16) {
        float sv[16];
        float cmx = -1e30f;
#pragma unroll
        for (int u = 0; u < 16; u++) {
            const float* kr = &Kst[(nt + u) * 8];
            float s = kr[0] * q[0] + kr[1] * q[1] + kr[2] * q[2] + kr[3] * q[3]
                    + kr[4] * q[4] + kr[5] * q[5] + kr[6] * q[6] + kr[7] * q[7];
            sv[u] = s;
            cmx = fmaxf(cmx, s);
        }
        if (cmx > mx) {
            sum *= __expf(mx - cmx);
            mx = cmx;
        }
#pragma unroll
        for (int u = 0; u < 16; u++) sum += __expf(sv[u] - mx);
    }
    d_mx[slab * M + j] = mx;
    d_ri[slab * M + j] = 1.f / sum;
}

// attention pass2 via tf32 mma.sync (round-7 proven version):
// D[128c x 64j] = V @ P, P recomputed on the fly (fp32 scores)
__global__ __launch_bounds__(256) void pass2_mma() {
    __shared__ uint32_t Vs[128][36];
    __shared__ uint32_t Ps[32][72];
    __shared__ float Ksh[32][8];
    __shared__ float Qs[8][64];
    __shared__ float mxs[64], ris[64];
    int tid = threadIdx.x;
    int slab = blockIdx.z, c0 = blockIdx.y * 128, j0 = blockIdx.x * 64;
    const float* base = d_qkvt + (size_t)slab * CATT * M;
    for (int i = tid; i < 512; i += 256) Qs[i >> 6][i & 63] = base[(i >> 6) * M + j0 + (i & 63)];
    if (tid < 64) {
        mxs[tid] = d_mx[slab * M + j0 + tid];
        ris[tid] = d_ri[slab * M + j0 + tid];
    }
    int wid = tid >> 5, lane = tid & 31, g = lane >> 2, t4 = lane & 3;
    int cw = (wid & 3) * 32, jw = (wid >> 2) * 32;
    float acc[2][4][4] = {};
    for (int t = 0; t < 32; t++) {
        int nt = t * 32;
        __syncthreads();
        { int c = tid & 7, n = tid >> 3; Ksh[n][c] = base[(8 + c) * M + nt + n]; }
#pragma unroll
        for (int i = 0; i < 4; i++) {
            int e = tid + i * 256, c = e >> 3, n4 = (e & 7) * 4;
            float4 v = *(const float4*)&base[(size_t)(16 + c0 + c) * M + nt + n4];
            uint4 u = make_uint4(f2tf(v.x), f2tf(v.y), f2tf(v.z), f2tf(v.w));
            *(uint4*)&Vs[c][n4] = u;
        }
        __syncthreads();
#pragma unroll
        for (int i = 0; i < 8; i++) {
            int e = tid + i * 256, n = e >> 6, j = e & 63;
            const float* kr = Ksh[n];
            float s = kr[0] * Qs[0][j] + kr[1] * Qs[1][j] + kr[2] * Qs[2][j] + kr[3] * Qs[3][j]
                    + kr[4] * Qs[4][j] + kr[5] * Qs[5][j] + kr[6] * Qs[6][j] + kr[7] * Qs[7][j];
            Ps[n][j] = f2tf(__expf(s - mxs[j]) * ris[j]);
        }
        __syncthreads();
#pragma unroll
        for (int kk = 0; kk < 32; kk += 8) {
            uint32_t a[2][4], bfr[4][2];
#pragma unroll
            for (int mt = 0; mt < 2; mt++) {
                int r0 = cw + mt * 16 + g;
                a[mt][0] = Vs[r0][kk + t4];     a[mt][1] = Vs[r0 + 8][kk + t4];
                a[mt][2] = Vs[r0][kk + t4 + 4]; a[mt][3] = Vs[r0 + 8][kk + t4 + 4];
            }
#pragma unroll
            for (int jt = 0; jt < 4; jt++) {
                bfr[jt][0] = Ps[kk + t4][jw + jt * 8 + g];
                bfr[jt][1] = Ps[kk + t4 + 4][jw + jt * 8 + g];
            }
#pragma unroll
            for (int mt = 0; mt < 2; mt++)
#pragma unroll
                for (int jt = 0; jt < 4; jt++)
                    mma8(acc[mt][jt], a[mt][0], a[mt][1], a[mt][2], a[mt][3], bfr[jt][0], bfr[jt][1]);
        }
    }
    float* afb = d_af + (size_t)slab * CF * M;
#pragma unroll
    for (int mt = 0; mt < 2; mt++)
#pragma unroll
        for (int jt = 0; jt < 4; jt++) {
            int c = c0 + cw + mt * 16 + g;
            int j = j0 + jw + jt * 8 + 2 * t4;
            *(float2*)&afb[(size_t)c * M + j]       = make_float2(acc[mt][jt][0], acc[mt][jt][1]);
            *(float2*)&afb[(size_t)(c + 8) * M + j] = make_float2(acc[mt][jt][2], acc[mt][jt][3]);
        }
}

__global__ void pool_k() {
    int i = blockIdx.x * 256 + threadIdx.x;
    if (i >= B * C3 * M) return;
    int m = i & 1023, c = (i >> 10) & 255, b = i >> 18;
    float sc = d_bnsc[OP + c], sh = d_bnsh[OP + c];
    float acc = -1e30f;
    for (int s = 0; s < 16; s++) {
        size_t slab = (size_t)(b * 16 + s);
        float z = d_zf[slab * CF * M + (size_t)c * M + m];
        float gf = d_ipt[slab * CAIN * M + (size_t)c * M + m];
        acc = fmaxf(acc, fmaxf(sc * z + sh, 0.f) + gf);
    }
    d_pooled[((size_t)b * C3 + c) * M + m] = acc;
}

__global__ void out_k(float* __restrict__ out) {
    int i = blockIdx.x * 256 + threadIdx.x;
    if (i >= B * CO * M) return;
    int c = (i >> 10) & 511;
    float z = d_zo[i];
    out[i] = fmaxf(d_bnsc[OO + c] * z + d_bnsh[OO + c], 0.f);
}

__global__ void ctr_k(const float* __restrict__ ctr, float* __restrict__ out, int n) {
    int i = blockIdx.x * 256 + threadIdx.x;
    if (i < n) out[i] = ctr[i];
}

extern "C" void kernel_launch(void* const* d_in, const int* in_sizes, int n_in,
                              void* d_out, int out_size) {
    (void)in_sizes; (void)n_in;
    const float* xyz = (const float*)d_in[0];
    const float* feat = (const float*)d_in[1];
    const float* ctr = (const float*)d_in[2];
    const float* W1 = (const float*)d_in[3];
    const float* g1 = (const float*)d_in[4];
    const float* b1 = (const float*)d_in[5];
    const float* W2 = (const float*)d_in[6];
    const float* g2 = (const float*)d_in[7];
    const float* b2 = (const float*)d_in[8];
    const float* W3 = (const float*)d_in[9];
    const float* g3 = (const float*)d_in[10];
    const float* b3 = (const float*)d_in[11];
    const float* Wq = (const float*)d_in[12];
    const float* Wk = (const float*)d_in[13];
    const float* Wv = (const float*)d_in[14];
    const float* Wf = (const float*)d_in[15];
    const float* gp = (const float*)d_in[16];
    const float* bp = (const float*)d_in[17];
    const float* Wo = (const float*)d_in[18];
    const float* go = (const float*)d_in[19];
    const float* bo = (const float*)d_in[20];
    float* outp = (float*)d_out;

    float *p_featin, *p_z1, *p_z2, *p_z3, *p_ipt, *p_wqkv, *p_qkvt, *p_af, *p_zf, *p_pooled, *p_zo;
    int *p_idx1, *p_idx2;
    cudaGetSymbolAddress((void**)&p_featin, d_featin);
    cudaGetSymbolAddress((void**)&p_z1, d_z1);
    cudaGetSymbolAddress((void**)&p_z2, d_z2);
    cudaGetSymbolAddress((void**)&p_z3, d_z3);
    cudaGetSymbolAddress((void**)&p_ipt, d_ipt);
    cudaGetSymbolAddress((void**)&p_wqkv, d_wqkv);
    cudaGetSymbolAddress((void**)&p_qkvt, d_qkvt);
    cudaGetSymbolAddress((void**)&p_af, d_af);
    cudaGetSymbolAddress((void**)&p_zf, d_zf);
    cudaGetSymbolAddress((void**)&p_pooled, d_pooled);
    cudaGetSymbolAddress((void**)&p_zo, d_zo);
    cudaGetSymbolAddress((void**)&p_idx1, d_idx1);
    cudaGetSymbolAddress((void**)&p_idx2, d_idx2);

    prep_featin_k<<<(B * C1IN * N + 255) / 256, 256>>>(xyz, feat);
    wqkv_k<<<(CATT * CAIN + 255) / 256, 256>>>(Wq, Wk, Wv);
    gemm_k<0><<<dim3(N / 64, 1, B), 256>>>(W1, p_featin, nullptr, p_z1, 64, C1IN, N,
                                           (size_t)C1IN * N, 0, (size_t)64 * N, 0);
    stats_k<<<64, 256>>>(p_z1, g1, b1, O1, B, 64, N);
    gemm_k<1><<<dim3(N / 64, 2, B), 256>>>(W2, p_z1, nullptr, p_z2, 128, 64, N,
                                           (size_t)64 * N, 0, (size_t)128 * N, O1);
    stats_k<<<128, 256>>>(p_z2, g2, b2, O2, B, 128, N);
    gemm_k<1><<<dim3(N / 64, 4, B), 256>>>(W3, p_z2, nullptr, p_z3, 256, 128, N,
                                           (size_t)128 * N, 0, (size_t)256 * N, O2);
    stats_k<<<256, 256>>>(p_z3, g3, b3, O3, B, 256, N);
    nft_k<<<dim3(N / 32, C3 / 32, B), dim3(32, 8)>>>();

    ballq_k<<<B * M / 8, 256>>>(xyz, N, ctr, p_idx1);
    ballq_k<<<B * M / 8, 256>>>(ctr, M, ctr, p_idx2);
    group_k<<<dim3(M / 32, 16, B), 256>>>(xyz, ctr);

    // q/k projection exact fp32; V projection tf32 tensor path
    qk_k<<<dim3(M / 256, SLAB), 256>>>();
    gemm_tc<0><<<dim3(M / 64, 4, SLAB), 256>>>(p_wqkv + 16 * CAIN, p_ipt, nullptr, p_qkvt + 16 * M,
                                               256, CAIN, M,
                                               (size_t)CAIN * M, 0, (size_t)CATT * M, 0);
    pass1_k<<<dim3(M / 256, SLAB), 256>>>();
    pass2_mma<<<dim3(M / 64, CF / 128, SLAB), 256>>>();

    gemm_tc<2><<<dim3(M / 64, 4, SLAB), 256>>>(Wf, p_af, p_ipt, p_zf, 256, 256, M,
                                               (size_t)CF * M, (size_t)CAIN * M, (size_t)CF * M, 0);
    stats_k<<<256, 256>>>(p_zf, gp, bp, OP, SLAB, 256, M);
    pool_k<<<(B * C3 * M + 255) / 256, 256>>>();

    // Wo: output-side tf32 (post-pooling, no exp downstream)
    gemm_tc<0><<<dim3(M / 64, 8, B), 256>>>(Wo, p_pooled, nullptr, p_zo, 512, 256, M,
                                            (size_t)CF * M, 0, (size_t)CO * M, 0);
    stats_k<<<512, 256>>>(p_zo, go, bo, OO, B, 512, M);

    int off = out_size - B * CO * M;
    if (off > 0) ctr_k<<<(off + 255) / 256, 256>>>(ctr, outp, off);
    out_k<<<(B * CO * M + 255) / 256, 256>>>(outp + (off > 0 ? off : 0));
}